// round 10
// baseline (speedup 1.0000x reference)
#include <cuda_runtime.h>
#include <cuda_fp16.h>
#include <cstdint>

// Problem dims
#define BZc   8
#define NUMc  1024
#define NAc   64
#define FDc   128
#define GRPS  8          // (b,p) groups per CTA

typedef unsigned int u32;

// ---------------- helpers ----------------
__device__ __forceinline__ float tanha(float x) {           // HW approx, hidden only
    float y; asm("tanh.approx.f32 %0, %1;" : "=f"(y) : "f"(x)); return y;
}
// Fast precise tanh: ex2 + rcp + 1 Newton step (~4e-7). Head/logit path.
__device__ __forceinline__ float tanhp(float x) {
    float t; asm("ex2.approx.f32 %0, %1;" : "=f"(t) : "f"(x * 2.8853900817779268f));
    float d = 1.0f + t;
    float r; asm("rcp.approx.f32 %0, %1;" : "=f"(r) : "f"(d));
    r = fmaf(fmaf(-d, r, 1.0f), r, r);
    return fmaf(-2.0f, r, 1.0f);
}
__device__ __forceinline__ u32 pkh2(float a, float b) {
    __half2 h = __floats2half2_rn(a, b);
    return *(u32*)&h;
}
__device__ __forceinline__ void mma_f16(float d[4],
    u32 a0, u32 a1, u32 a2, u32 a3, u32 b0, u32 b1)
{
    asm("mma.sync.aligned.m16n8k16.row.col.f32.f16.f16.f32 "
        "{%0,%1,%2,%3}, {%4,%5,%6,%7}, {%8,%9}, {%0,%1,%2,%3};"
        : "+f"(d[0]), "+f"(d[1]), "+f"(d[2]), "+f"(d[3])
        : "r"(a0), "r"(a1), "r"(a2), "r"(a3), "r"(b0), "r"(b1));
}

// ---------------- folded weight storage (fp16 fragment layouts) ----------------
__device__ uint4 g_WhF[4 * 8 * 32];   // A1 frags [tile(4)][kk(8)][lane(32)]
__device__ uint4 g_M2hF[2 * 5 * 32];  // M2 frags [m(2)][kk2(5)][lane(32)]
__device__ float g_c1[64];
__device__ float g_ca[32];
__device__ float g_B1[8][4];
__device__ float g_d1[8];
__device__ float g_B2[16][8];
__device__ float g_d2[16];
__device__ float g_Wa2[32];
__device__ float g_ba2s;

// ---------------- weight folding kernel ----------------
__global__ void disarm_prep(
    const float* __restrict__ Wf1, const float* __restrict__ bf1,
    const float* __restrict__ gf1, const float* __restrict__ btf1,
    const float* __restrict__ Wf2, const float* __restrict__ bf2,
    const float* __restrict__ Ws1, const float* __restrict__ bs1,
    const float* __restrict__ gs1, const float* __restrict__ bts1,
    const float* __restrict__ Ws2, const float* __restrict__ bs2,
    const float* __restrict__ gs2, const float* __restrict__ bts2,
    const float* __restrict__ Ws3, const float* __restrict__ bs3,
    const float* __restrict__ Wa1, const float* __restrict__ ba1,
    const float* __restrict__ ga1, const float* __restrict__ bta1,
    const float* __restrict__ Wa2, const float* __restrict__ ba2)
{
    const float inv = rsqrtf(1.0f + 1e-5f);
    const int t = threadIdx.x;
    const int nt = blockDim.x;

    auto wt = [&](int r, int c) -> float {
        return gf1[r] * inv * Wf1[r * FDc + c];
    };
    for (int i = t; i < 4 * 8 * 32; i += nt) {
        int tile = i >> 8, kk = (i >> 5) & 7, lane = i & 31;
        int g8 = lane >> 2, t4 = lane & 3;
        int r = 16 * tile + g8, c = 16 * kk + 2 * t4;
        uint4 v;
        v.x = pkh2(wt(r,     c), wt(r,     c + 1));
        v.y = pkh2(wt(r + 8, c), wt(r + 8, c + 1));
        v.z = pkh2(wt(r,     c + 8), wt(r,     c + 9));
        v.w = pkh2(wt(r + 8, c + 8), wt(r + 8, c + 9));
        g_WhF[i] = v;
    }
    auto m2 = [&](int o, int kk) -> float {
        float acc = 0.0f;
        if (kk < 64) {
            for (int j = 0; j < 32; ++j) acc += Wa1[o*64 + 32 + j] * Wf2[j*64 + kk];
        } else {
            for (int mq = 0; mq < 32; ++mq) acc += Wa1[o*64 + mq] * Ws3[mq*16 + (kk - 64)];
        }
        return ga1[o] * inv * acc;
    };
    // k-pair unit map: pair p<32 -> hidden rows (16(p>>3)+(p&7)), +8;
    //                  p>=32 -> spatial units 2(p-32), +1
    auto U = [&](int p, int e) -> int {
        if (p < 32) return 16 * (p >> 3) + (p & 7) + 8 * e;
        return 64 + 2 * (p - 32) + e;
    };
    for (int i = t; i < 2 * 5 * 32; i += nt) {
        int m = i / (5 * 32), kk2 = (i / 32) % 5, lane = i & 31;
        int g8 = lane >> 2, t4 = lane & 3;
        int r = 16 * m + g8;
        int p = 8 * kk2 + t4;
        uint4 v;
        v.x = pkh2(m2(r,     U(p, 0)),     m2(r,     U(p, 1)));
        v.y = pkh2(m2(r + 8, U(p, 0)),     m2(r + 8, U(p, 1)));
        v.z = pkh2(m2(r,     U(p + 4, 0)), m2(r,     U(p + 4, 1)));
        v.w = pkh2(m2(r + 8, U(p + 4, 0)), m2(r + 8, U(p + 4, 1)));
        g_M2hF[i] = v;
    }
    for (int i = t; i < 64; i += nt) g_c1[i] = gf1[i]*inv*bf1[i] + btf1[i];
    if (t < 32) {
        float acc = 0.0f;
        for (int j = 0; j < 32; ++j) acc += Wa1[t*64 + 32 + j] * bf2[j];
        for (int mq = 0; mq < 32; ++mq) acc += Wa1[t*64 + mq] * bs3[mq];
        g_ca[t] = ga1[t]*inv*(acc + ba1[t]) + bta1[t];
    }
    if (t < 8) {
        for (int i = 0; i < 3; ++i) g_B1[t][i] = gs1[t]*inv*Ws1[t*3 + i];
        g_B1[t][3] = 0.0f;
        g_d1[t] = gs1[t]*inv*bs1[t] + bts1[t];
    }
    if (t < 16) {
        for (int i = 0; i < 8; ++i) g_B2[t][i] = gs2[t]*inv*Ws2[t*8 + i];
        g_d2[t] = gs2[t]*inv*bs2[t] + bts2[t];
    }
    if (t < 32) g_Wa2[t] = Wa2[t];
    if (t == 0) g_ba2s = ba2[0];
}

// ---------------- smem layout (bytes) ----------------
#define XHS      72                         // u32 per channel-pair row
#define XHBUF    (64 * XHS * 4)             // 18432 B
#define CHS      72
#define SM_XH    0                          // 2 buffers: 36864
#define SM_CH    (2 * XHBUF)                // 40*72*4 = 11520
#define SM_PART  (SM_CH + 11520)            // 2 bufs * 2 * 64 * 4 = 1024
#define SM_C1    (SM_PART + 1024)           // 256
#define SM_CA    (SM_C1 + 256)              // 128
#define SM_WA2   (SM_CA + 128)              // 128
#define SM_B1    (SM_WA2 + 128)             // 128
#define SM_D1    (SM_B1 + 128)              // 32
#define SM_B2    (SM_D1 + 32)               // 512
#define SM_D2    (SM_B2 + 512)              // 64
#define SM_BA2   (SM_D2 + 64)               // 16
#define SM_TOTAL (SM_BA2 + 16)

// ---------------- main fused kernel ----------------
// Round-8 skeleton (2 syncs/group, in-loop tail). mma1 retiled to 32 rows x
// 16 anchors per warp: warp (wM2 = warp&1 -> rows 32wM2.., wN4 = warp>>1 ->
// anchors 16wN4..). Anchor perm within block: a = 16wN4 + 2c + n, so B loads
// are LDS.64 pairs (tile n=0/1 adjacent) and X is read only 2x (was 4x).
// A1 frags: 64 persistent regs (2 row tiles). M2 frags reloaded per group.
__global__ void __launch_bounds__(256, 2) disarm_mma(
    const float* __restrict__ loc, const float* __restrict__ feat,
    float* __restrict__ out)
{
    extern __shared__ char smem[];
    u32* sXH = (u32*)(smem + SM_XH);
    u32* sCH = (u32*)(smem + SM_CH);
    float (*sPart)[2][64] = (float (*)[2][64])(smem + SM_PART);  // [buf][m][a]
    float* sc1   = (float*)(smem + SM_C1);
    float* sca   = (float*)(smem + SM_CA);
    float* sWa2v = (float*)(smem + SM_WA2);
    float (*sB1)[4] = (float (*)[4])(smem + SM_B1);
    float* sd1   = (float*)(smem + SM_D1);
    float (*sB2)[8] = (float (*)[8])(smem + SM_B2);
    float* sd2   = (float*)(smem + SM_D2);
    float* sba2  = (float*)(smem + SM_BA2);

    const int tid  = threadIdx.x;
    const int warp = tid >> 5;
    const int lane = tid & 31;
    const int g8   = lane >> 2;
    const int t4   = lane & 3;
    const int wM2  = warp & 1;    // mma1 row half (rows 32*wM2..+31)
    const int wN4  = warp >> 1;   // mma1 anchor 16-block (0..3)
    const int m    = warp & 1;    // mma2 row half
    const int nt   = warp >> 1;   // mma2 anchor 16-col tile

    const size_t cs = (size_t)NUMc * NAc;
    const int gp0 = blockIdx.x * GRPS;

    // ---- persistent A1 fragments: 2 row tiles, 16 coalesced LDG.128 ----
    u32 A0[32], A1[32];
    {
        const uint4* aw0 = g_WhF + (size_t)(2*wM2    ) * 8 * 32 + lane;
        const uint4* aw1 = g_WhF + (size_t)(2*wM2 + 1) * 8 * 32 + lane;
        #pragma unroll
        for (int kk = 0; kk < 8; ++kk) {
            uint4 v = __ldg(aw0 + kk * 32);
            A0[4*kk+0] = v.x; A0[4*kk+1] = v.y; A0[4*kk+2] = v.z; A0[4*kk+3] = v.w;
            uint4 w = __ldg(aw1 + kk * 32);
            A1[4*kk+0] = w.x; A1[4*kk+1] = w.y; A1[4*kk+2] = w.z; A1[4*kk+3] = w.w;
        }
    }

    // ---- stage small weights ----
    if (tid < 64) sc1[tid] = g_c1[tid];
    if (tid < 32) { sca[tid] = g_ca[tid]; sWa2v[tid] = g_Wa2[tid]; }
    if (tid < 32) sB1[tid>>2][tid&3] = g_B1[tid>>2][tid&3];
    if (tid < 8)  sd1[tid] = g_d1[tid];
    if (tid >= 128 && tid < 256) sB2[(tid-128)>>3][(tid-128)&7] = g_B2[(tid-128)>>3][(tid-128)&7];
    if (tid < 16) sd2[tid] = g_d2[tid];
    if (tid == 0) sba2[0] = g_ba2s;

    // per-thread convert indices: 4 iters of (channel-pair, anchor-block)
    int cpi[4], abi[4];
    #pragma unroll
    for (int it = 0; it < 4; ++it) {
        int i = tid + 256 * it;
        cpi[it] = i >> 4;
        abi[it] = i & 15;
    }

    // ---- prologue: fill X half tile for group 0 ----
    {
        const int b = gp0 >> 10, p = gp0 & 1023;
        const float* fb = feat + (size_t)b * FDc * cs + (size_t)p * NAc;
        #pragma unroll
        for (int it = 0; it < 4; ++it) {
            const int cp = cpi[it], ab = abi[it];
            float4 xa = __ldg((const float4*)(fb + (size_t)(2*cp  ) * cs) + ab);
            float4 xc = __ldg((const float4*)(fb + (size_t)(2*cp+1) * cs) + ab);
            uint4 w;
            w.x = pkh2(xa.x, xc.x); w.y = pkh2(xa.y, xc.y);
            w.z = pkh2(xa.z, xc.z); w.w = pkh2(xa.w, xc.w);
            *(uint4*)(sXH + cp * XHS + 4 * ab) = w;
        }
    }
    __syncthreads();

    const int sa  = tid & 63;       // spatial anchor
    const int sos = tid >> 6;       // spatial output slice (4 outputs)

    #pragma unroll 1
    for (int g = 0; g < GRPS; ++g) {
        const int gp = gp0 + g;
        const int b  = gp >> 10;
        const int p  = gp & 1023;
        u32* xb = sXH + (g & 1) * (64 * XHS);

        // ---- prefetch group g+1's X into registers ----
        float4 q0a, q0b, q1a, q1b, q2a, q2b, q3a, q3b;
        if (g + 1 < GRPS) {
            const int gp1 = gp + 1;
            const int b1 = gp1 >> 10, p1 = gp1 & 1023;
            const float* fb1 = feat + (size_t)b1 * FDc * cs + (size_t)p1 * NAc;
            q0a = __ldg((const float4*)(fb1 + (size_t)(2*cpi[0]  ) * cs) + abi[0]);
            q0b = __ldg((const float4*)(fb1 + (size_t)(2*cpi[0]+1) * cs) + abi[0]);
            q1a = __ldg((const float4*)(fb1 + (size_t)(2*cpi[1]  ) * cs) + abi[1]);
            q1b = __ldg((const float4*)(fb1 + (size_t)(2*cpi[1]+1) * cs) + abi[1]);
            q2a = __ldg((const float4*)(fb1 + (size_t)(2*cpi[2]  ) * cs) + abi[2]);
            q2b = __ldg((const float4*)(fb1 + (size_t)(2*cpi[2]+1) * cs) + abi[2]);
            q3a = __ldg((const float4*)(fb1 + (size_t)(2*cpi[3]  ) * cs) + abi[3]);
            q3b = __ldg((const float4*)(fb1 + (size_t)(2*cpi[3]+1) * cs) + abi[3]);
        }

        // early loc load
        const float* lp = loc + (((size_t)(b*NUMc + p))*NAc + sa) * 3;
        const float l0 = __ldg(lp), l1 = __ldg(lp + 1), l2 = __ldg(lp + 2);

        // ---- mma1: 32 fp16 mma/warp, 2 LDS.64 per kstep (2x reuse) ----
        float D[2][2][4];
        #pragma unroll
        for (int r = 0; r < 2; ++r)
            #pragma unroll
            for (int n = 0; n < 2; ++n)
                { D[r][n][0]=0.f; D[r][n][1]=0.f; D[r][n][2]=0.f; D[r][n][3]=0.f; }
        #pragma unroll
        for (int kk = 0; kk < 8; ++kk) {
            const uint2 v0 = *(const uint2*)(xb + (8*kk + t4    ) * XHS + 16*wN4 + 2*g8);
            const uint2 v1 = *(const uint2*)(xb + (8*kk + t4 + 4) * XHS + 16*wN4 + 2*g8);
            mma_f16(D[0][0], A0[4*kk], A0[4*kk+1], A0[4*kk+2], A0[4*kk+3], v0.x, v1.x);
            mma_f16(D[0][1], A0[4*kk], A0[4*kk+1], A0[4*kk+2], A0[4*kk+3], v0.y, v1.y);
            mma_f16(D[1][0], A1[4*kk], A1[4*kk+1], A1[4*kk+2], A1[4*kk+3], v0.x, v1.x);
            mma_f16(D[1][1], A1[4*kk], A1[4*kk+1], A1[4*kk+2], A1[4*kk+3], v0.y, v1.y);
        }

        // ---- spatial branch -> C k-pairs 32..39 ----
        {
            float s1v[8];
            #pragma unroll
            for (int j = 0; j < 8; ++j)
                s1v[j] = tanha(sB1[j][0]*l0 + sB1[j][1]*l1 + sB1[j][2]*l2 + sd1[j]);
            float acc0 = sd2[4*sos+0], acc1 = sd2[4*sos+1];
            float acc2 = sd2[4*sos+2], acc3 = sd2[4*sos+3];
            #pragma unroll
            for (int i = 0; i < 8; ++i) {
                acc0 += sB2[4*sos+0][i] * s1v[i];
                acc1 += sB2[4*sos+1][i] * s1v[i];
                acc2 += sB2[4*sos+2][i] * s1v[i];
                acc3 += sB2[4*sos+3][i] * s1v[i];
            }
            sCH[(32 + 2*sos) * CHS + sa] = pkh2(tanha(acc0), tanha(acc1));
            sCH[(33 + 2*sos) * CHS + sa] = pkh2(tanha(acc2), tanha(acc3));
        }

        // ---- epi1: tanh(H + c1) -> C k-pairs (2 STS.128) ----
        // D[r][n] frag col 2t4+s -> anchor 16wN4 + 4t4 + 2s + n
        #pragma unroll
        for (int r = 0; r < 2; ++r) {
            const int tile = 2*wM2 + r;
            const int pp = 8*tile + g8;
            const float c1a = sc1[16*tile + g8];
            const float c1b = sc1[16*tile + g8 + 8];
            u32* cw = sCH + pp * CHS + 16*wN4 + 4*t4;
            uint4 w;
            w.x = pkh2(tanha(D[r][0][0] + c1a), tanha(D[r][0][2] + c1b));
            w.y = pkh2(tanha(D[r][1][0] + c1a), tanha(D[r][1][2] + c1b));
            w.z = pkh2(tanha(D[r][0][1] + c1a), tanha(D[r][0][3] + c1b));
            w.w = pkh2(tanha(D[r][1][1] + c1a), tanha(D[r][1][3] + c1b));
            *(uint4*)cw = w;
        }
        __syncthreads();            // sC ready; xb reads done

        // ---- mma2: 10 fp16 mma/warp; M2 frags via L1-hit LDG.128 ----
        float D2[2][4];
        D2[0][0]=0.f; D2[0][1]=0.f; D2[0][2]=0.f; D2[0][3]=0.f;
        D2[1][0]=0.f; D2[1][1]=0.f; D2[1][2]=0.f; D2[1][3]=0.f;
        {
            const uint4* mw = g_M2hF + (size_t)m * 5 * 32 + lane;
            #pragma unroll
            for (int kk2 = 0; kk2 < 5; ++kk2) {
                const uint4 mv = __ldg(mw + kk2 * 32);
                const uint2 w0 = *(const uint2*)(sCH + (8*kk2 + t4    ) * CHS + 16*nt + 2*g8);
                const uint2 w1 = *(const uint2*)(sCH + (8*kk2 + t4 + 4) * CHS + 16*nt + 2*g8);
                mma_f16(D2[0], mv.x, mv.y, mv.z, mv.w, w0.x, w1.x);
                mma_f16(D2[1], mv.x, mv.y, mv.z, mv.w, w0.y, w1.y);
            }
        }

        // ---- epi2: head partials; D2[n2] col 2t4+s -> anchor 16nt+4t4+2s+n2 ----
        {
            const int ro = 16*m + g8;
            const float wa  = sWa2v[ro],   wb  = sWa2v[ro + 8];
            const float caa = sca[ro],     cab = sca[ro + 8];
            float p0 = wa * tanhp(D2[0][0] + caa) + wb * tanhp(D2[0][2] + cab); // +0
            float p2 = wa * tanhp(D2[1][0] + caa) + wb * tanhp(D2[1][2] + cab); // +1
            float p1 = wa * tanhp(D2[0][1] + caa) + wb * tanhp(D2[0][3] + cab); // +2
            float p3 = wa * tanhp(D2[1][1] + caa) + wb * tanhp(D2[1][3] + cab); // +3
            const unsigned m32 = 0xffffffffu;
            #pragma unroll
            for (int off = 4; off <= 16; off <<= 1) {
                p0 += __shfl_xor_sync(m32, p0, off);
                p1 += __shfl_xor_sync(m32, p1, off);
                p2 += __shfl_xor_sync(m32, p2, off);
                p3 += __shfl_xor_sync(m32, p3, off);
            }
            if (g8 == 0) {
                float4 v; v.x = p0; v.y = p2; v.z = p1; v.w = p3;
                *(float4*)&sPart[g & 1][m][16*nt + 4*t4] = v;
            }
        }

        // ---- convert + store X[g+1] (LDG latency fully elapsed by now) ----
        if (g + 1 < GRPS) {
            u32* xd = sXH + ((g + 1) & 1) * (64 * XHS);
            uint4 w;
            w.x = pkh2(q0a.x, q0b.x); w.y = pkh2(q0a.y, q0b.y);
            w.z = pkh2(q0a.z, q0b.z); w.w = pkh2(q0a.w, q0b.w);
            *(uint4*)(xd + cpi[0] * XHS + 4 * abi[0]) = w;
            w.x = pkh2(q1a.x, q1b.x); w.y = pkh2(q1a.y, q1b.y);
            w.z = pkh2(q1a.z, q1b.z); w.w = pkh2(q1a.w, q1b.w);
            *(uint4*)(xd + cpi[1] * XHS + 4 * abi[1]) = w;
            w.x = pkh2(q2a.x, q2b.x); w.y = pkh2(q2a.y, q2b.y);
            w.z = pkh2(q2a.z, q2b.z); w.w = pkh2(q2a.w, q2b.w);
            *(uint4*)(xd + cpi[2] * XHS + 4 * abi[2]) = w;
            w.x = pkh2(q3a.x, q3b.x); w.y = pkh2(q3a.y, q3b.y);
            w.z = pkh2(q3a.z, q3b.z); w.w = pkh2(q3a.w, q3b.w);
            *(uint4*)(xd + cpi[3] * XHS + 4 * abi[3]) = w;
        }
        __syncthreads();            // sPart + X[g+1] visible; sC reads done

        // ---- tail: warp 0 softmax + min-max norm (overlaps next mma1) ----
        if (warp == 0) {
            const int a0 = lane, a1 = lane + 32;
            const float* pb0 = sPart[g & 1][0];
            const float* pb1 = sPart[g & 1][1];
            const float lg0 = tanhp(pb0[a0] + pb1[a0] + sba2[0]);
            const float lg1 = tanhp(pb0[a1] + pb1[a1] + sba2[0]);

            const unsigned m32 = 0xffffffffu;
            float mx = fmaxf(lg0, lg1);
            float mn = fminf(lg0, lg1);
            #pragma unroll
            for (int off = 16; off > 0; off >>= 1) {
                mx = fmaxf(mx, __shfl_xor_sync(m32, mx, off));
                mn = fminf(mn, __shfl_xor_sync(m32, mn, off));
            }
            const float e0 = expf(lg0 - mx);
            const float e1 = expf(lg1 - mx);
            float ssum = e0 + e1;
            #pragma unroll
            for (int off = 16; off > 0; off >>= 1) ssum += __shfl_xor_sync(m32, ssum, off);
            const float invs = 1.0f / ssum;

            const float w0  = e0 * invs;
            const float w1  = e1 * invs;
            const float wmn = expf(mn - mx) * invs;
            const float wmx = invs;
            const float kk  = (1.0f + 1e-6f) / (wmx - wmn + 1e-6f);

            float* ob = out + (size_t)gp * NAc;
            float* on = ob + (size_t)BZc * NUMc * NAc;
            ob[a0] = w0;
            ob[a1] = w1;
            on[a0] = kk * (w0 - wmn);
            on[a1] = kk * (w1 - wmn);
        }
    }
}

// ---------------- launch ----------------
extern "C" void kernel_launch(void* const* d_in, const int* in_sizes, int n_in,
                              void* d_out, int out_size)
{
    const float* loc  = (const float*)d_in[0];
    const float* feat = (const float*)d_in[1];

    disarm_prep<<<1, 256>>>(
        (const float*)d_in[2],  (const float*)d_in[3],  (const float*)d_in[4],  (const float*)d_in[5],
        (const float*)d_in[6],  (const float*)d_in[7],
        (const float*)d_in[8],  (const float*)d_in[9],  (const float*)d_in[10], (const float*)d_in[11],
        (const float*)d_in[12], (const float*)d_in[13], (const float*)d_in[14], (const float*)d_in[15],
        (const float*)d_in[16], (const float*)d_in[17],
        (const float*)d_in[18], (const float*)d_in[19], (const float*)d_in[20], (const float*)d_in[21],
        (const float*)d_in[22], (const float*)d_in[23]);

    static int smem_set = 0;
    if (!smem_set) {
        cudaFuncSetAttribute(disarm_mma,
                             cudaFuncAttributeMaxDynamicSharedMemorySize, SM_TOTAL);
        smem_set = 1;
    }
    disarm_mma<<<(BZc * NUMc) / GRPS, 256, SM_TOTAL>>>(loc, feat, (float*)d_out);
}

// round 11
// speedup vs baseline: 1.1760x; 1.1760x over previous
#include <cuda_runtime.h>
#include <cuda_fp16.h>
#include <cstdint>

// Problem dims
#define BZc   8
#define NUMc  1024
#define NAc   64
#define FDc   128
#define GRPS  8          // (b,p) groups per CTA

typedef unsigned int u32;

// ---------------- helpers ----------------
__device__ __forceinline__ float tanha(float x) {           // HW approx, hidden only
    float y; asm("tanh.approx.f32 %0, %1;" : "=f"(y) : "f"(x)); return y;
}
// Fast precise tanh: ex2 + rcp + 1 Newton step (~4e-7). Head/logit path.
__device__ __forceinline__ float tanhp(float x) {
    float t; asm("ex2.approx.f32 %0, %1;" : "=f"(t) : "f"(x * 2.8853900817779268f));
    float d = 1.0f + t;
    float r; asm("rcp.approx.f32 %0, %1;" : "=f"(r) : "f"(d));
    r = fmaf(fmaf(-d, r, 1.0f), r, r);
    return fmaf(-2.0f, r, 1.0f);
}
__device__ __forceinline__ u32 pkh2(float a, float b) {
    __half2 h = __floats2half2_rn(a, b);
    return *(u32*)&h;
}
__device__ __forceinline__ void mma_f16(float d[4],
    u32 a0, u32 a1, u32 a2, u32 a3, u32 b0, u32 b1)
{
    asm("mma.sync.aligned.m16n8k16.row.col.f32.f16.f16.f32 "
        "{%0,%1,%2,%3}, {%4,%5,%6,%7}, {%8,%9}, {%0,%1,%2,%3};"
        : "+f"(d[0]), "+f"(d[1]), "+f"(d[2]), "+f"(d[3])
        : "r"(a0), "r"(a1), "r"(a2), "r"(a3), "r"(b0), "r"(b1));
}

// ---------------- folded weight storage (fp16 fragment layouts) ----------------
__device__ uint4 g_WhF[4 * 8 * 32];   // A1 frags [tile(4)][kk(8)][lane(32)]
__device__ uint4 g_M2hF[2 * 5 * 32];  // M2 frags [m(2)][kk2(5)][lane(32)]
__device__ float g_c1[64];
__device__ float g_ca[32];
__device__ float g_B1[8][4];
__device__ float g_d1[8];
__device__ float g_B2[16][8];
__device__ float g_d2[16];
__device__ float g_Wa2[32];
__device__ float g_ba2s;

// ---------------- weight folding kernel ----------------
__global__ void disarm_prep(
    const float* __restrict__ Wf1, const float* __restrict__ bf1,
    const float* __restrict__ gf1, const float* __restrict__ btf1,
    const float* __restrict__ Wf2, const float* __restrict__ bf2,
    const float* __restrict__ Ws1, const float* __restrict__ bs1,
    const float* __restrict__ gs1, const float* __restrict__ bts1,
    const float* __restrict__ Ws2, const float* __restrict__ bs2,
    const float* __restrict__ gs2, const float* __restrict__ bts2,
    const float* __restrict__ Ws3, const float* __restrict__ bs3,
    const float* __restrict__ Wa1, const float* __restrict__ ba1,
    const float* __restrict__ ga1, const float* __restrict__ bta1,
    const float* __restrict__ Wa2, const float* __restrict__ ba2)
{
    const float inv = rsqrtf(1.0f + 1e-5f);
    const int t = threadIdx.x;
    const int nt = blockDim.x;

    auto wt = [&](int r, int c) -> float {
        return gf1[r] * inv * Wf1[r * FDc + c];
    };
    for (int i = t; i < 4 * 8 * 32; i += nt) {
        int tile = i >> 8, kk = (i >> 5) & 7, lane = i & 31;
        int g8 = lane >> 2, t4 = lane & 3;
        int r = 16 * tile + g8, c = 16 * kk + 2 * t4;
        uint4 v;
        v.x = pkh2(wt(r,     c), wt(r,     c + 1));
        v.y = pkh2(wt(r + 8, c), wt(r + 8, c + 1));
        v.z = pkh2(wt(r,     c + 8), wt(r,     c + 9));
        v.w = pkh2(wt(r + 8, c + 8), wt(r + 8, c + 9));
        g_WhF[i] = v;
    }
    auto m2 = [&](int o, int kk) -> float {
        float acc = 0.0f;
        if (kk < 64) {
            for (int j = 0; j < 32; ++j) acc += Wa1[o*64 + 32 + j] * Wf2[j*64 + kk];
        } else {
            for (int mq = 0; mq < 32; ++mq) acc += Wa1[o*64 + mq] * Ws3[mq*16 + (kk - 64)];
        }
        return ga1[o] * inv * acc;
    };
    // k-pair unit map: pair p<32 -> hidden rows (16(p>>3)+(p&7)), +8;
    //                  p>=32 -> spatial units 2(p-32), +1
    auto U = [&](int p, int e) -> int {
        if (p < 32) return 16 * (p >> 3) + (p & 7) + 8 * e;
        return 64 + 2 * (p - 32) + e;
    };
    for (int i = t; i < 2 * 5 * 32; i += nt) {
        int m = i / (5 * 32), kk2 = (i / 32) % 5, lane = i & 31;
        int g8 = lane >> 2, t4 = lane & 3;
        int r = 16 * m + g8;
        int p = 8 * kk2 + t4;
        uint4 v;
        v.x = pkh2(m2(r,     U(p, 0)),     m2(r,     U(p, 1)));
        v.y = pkh2(m2(r + 8, U(p, 0)),     m2(r + 8, U(p, 1)));
        v.z = pkh2(m2(r,     U(p + 4, 0)), m2(r,     U(p + 4, 1)));
        v.w = pkh2(m2(r + 8, U(p + 4, 0)), m2(r + 8, U(p + 4, 1)));
        g_M2hF[i] = v;
    }
    for (int i = t; i < 64; i += nt) g_c1[i] = gf1[i]*inv*bf1[i] + btf1[i];
    if (t < 32) {
        float acc = 0.0f;
        for (int j = 0; j < 32; ++j) acc += Wa1[t*64 + 32 + j] * bf2[j];
        for (int mq = 0; mq < 32; ++mq) acc += Wa1[t*64 + mq] * bs3[mq];
        g_ca[t] = ga1[t]*inv*(acc + ba1[t]) + bta1[t];
    }
    if (t < 8) {
        for (int i = 0; i < 3; ++i) g_B1[t][i] = gs1[t]*inv*Ws1[t*3 + i];
        g_B1[t][3] = 0.0f;
        g_d1[t] = gs1[t]*inv*bs1[t] + bts1[t];
    }
    if (t < 16) {
        for (int i = 0; i < 8; ++i) g_B2[t][i] = gs2[t]*inv*Ws2[t*8 + i];
        g_d2[t] = gs2[t]*inv*bs2[t] + bts2[t];
    }
    if (t < 32) g_Wa2[t] = Wa2[t];
    if (t == 0) g_ba2s = ba2[0];
}

// ---------------- smem layout (bytes) ----------------
#define XHS      72                         // u32 per channel-pair row
#define XHBUF    (64 * XHS * 4)             // 18432 B
#define CHS      72
#define SM_XH    0                          // 2 buffers: 36864
#define SM_CH    (2 * XHBUF)                // 40*72*4 = 11520
#define SM_PART  (SM_CH + 11520)            // 2 bufs * 2 * 64 * 4 = 1024
#define SM_C1    (SM_PART + 1024)           // 256
#define SM_CA    (SM_C1 + 256)              // 128
#define SM_WA2   (SM_CA + 128)              // 128
#define SM_B1    (SM_WA2 + 128)             // 128
#define SM_D1    (SM_B1 + 128)              // 32
#define SM_B2    (SM_D1 + 32)               // 512
#define SM_D2    (SM_B2 + 512)              // 64
#define SM_BA2   (SM_D2 + 64)               // 16
#define SM_TOTAL (SM_BA2 + 16)

// ---------------- main fused kernel ----------------
// Round-8 algorithm exactly; register-pressure fixes only:
//  - X[g+1] prefetch LDGs issued AFTER mma1 (q regs no longer live across the
//    hot mma1 window; latency still covered by spatial+epi1+sync+mma2+epi2)
//  - index arrays folded to scalars (abi invariant = tid&15; cpi = tid>>4 + 16it)
__global__ void __launch_bounds__(256, 2) disarm_mma(
    const float* __restrict__ loc, const float* __restrict__ feat,
    float* __restrict__ out)
{
    extern __shared__ char smem[];
    u32* sXH = (u32*)(smem + SM_XH);
    u32* sCH = (u32*)(smem + SM_CH);
    float (*sPart)[2][64] = (float (*)[2][64])(smem + SM_PART);  // [buf][m][a]
    float* sc1   = (float*)(smem + SM_C1);
    float* sca   = (float*)(smem + SM_CA);
    float* sWa2v = (float*)(smem + SM_WA2);
    float (*sB1)[4] = (float (*)[4])(smem + SM_B1);
    float* sd1   = (float*)(smem + SM_D1);
    float (*sB2)[8] = (float (*)[8])(smem + SM_B2);
    float* sd2   = (float*)(smem + SM_D2);
    float* sba2  = (float*)(smem + SM_BA2);

    const int tid  = threadIdx.x;
    const int warp = tid >> 5;
    const int lane = tid & 31;
    const int g8   = lane >> 2;
    const int t4   = lane & 3;
    const int wM   = warp >> 1;   // mma1 row tile (0..3)
    const int wN   = warp & 1;    // mma1 anchor half (0..1)
    const int m    = warp & 1;    // mma2 row half
    const int nt   = warp >> 1;   // mma2 anchor 16-col tile

    const size_t cs = (size_t)NUMc * NAc;
    const int gp0 = blockIdx.x * GRPS;

    // X-staging indices (iteration-invariant parts folded to scalars)
    const int cp0 = tid >> 4;      // channel-pair base; iter it uses cp0 + 16*it
    const int ab  = tid & 15;      // anchor block (same for all it)

    // ---- persistent A1 fragments (8 coalesced LDG.128) ----
    u32 A[32];
    {
        const uint4* aw = g_WhF + (size_t)wM * 8 * 32 + lane;
        #pragma unroll
        for (int kk = 0; kk < 8; ++kk) {
            uint4 v = __ldg(aw + kk * 32);
            A[4*kk+0] = v.x; A[4*kk+1] = v.y; A[4*kk+2] = v.z; A[4*kk+3] = v.w;
        }
    }
    // ---- persistent M2 fragments (5 coalesced LDG.128) ----
    u32 M[20];
    {
        const uint4* mw = g_M2hF + (size_t)m * 5 * 32 + lane;
        #pragma unroll
        for (int kk2 = 0; kk2 < 5; ++kk2) {
            uint4 v = __ldg(mw + kk2 * 32);
            M[4*kk2+0] = v.x; M[4*kk2+1] = v.y; M[4*kk2+2] = v.z; M[4*kk2+3] = v.w;
        }
    }

    // ---- stage small weights ----
    if (tid < 64) sc1[tid] = g_c1[tid];
    if (tid < 32) { sca[tid] = g_ca[tid]; sWa2v[tid] = g_Wa2[tid]; }
    if (tid < 32) sB1[tid>>2][tid&3] = g_B1[tid>>2][tid&3];
    if (tid < 8)  sd1[tid] = g_d1[tid];
    if (tid >= 128 && tid < 256) sB2[(tid-128)>>3][(tid-128)&7] = g_B2[(tid-128)>>3][(tid-128)&7];
    if (tid < 16) sd2[tid] = g_d2[tid];
    if (tid == 0) sba2[0] = g_ba2s;

    // ---- prologue: fill X half tile for group 0 ----
    {
        const int b = gp0 >> 10, p = gp0 & 1023;
        const float* fb = feat + (size_t)b * FDc * cs + (size_t)p * NAc;
        #pragma unroll
        for (int it = 0; it < 4; ++it) {
            const int cp = cp0 + 16 * it;
            float4 xa = __ldg((const float4*)(fb + (size_t)(2*cp  ) * cs) + ab);
            float4 xc = __ldg((const float4*)(fb + (size_t)(2*cp+1) * cs) + ab);
            uint4 w;
            w.x = pkh2(xa.x, xc.x); w.y = pkh2(xa.y, xc.y);
            w.z = pkh2(xa.z, xc.z); w.w = pkh2(xa.w, xc.w);
            *(uint4*)(sXH + cp * XHS + 4 * ab) = w;
        }
    }
    __syncthreads();

    const int sa  = tid & 63;       // spatial anchor
    const int sos = tid >> 6;       // spatial output slice (4 outputs)

    #pragma unroll 1
    for (int g = 0; g < GRPS; ++g) {
        const int gp = gp0 + g;
        const int b  = gp >> 10;
        const int p  = gp & 1023;
        u32* xb = sXH + (g & 1) * (64 * XHS);

        // early loc load (latency hides under mma1)
        const float* lp = loc + (((size_t)(b*NUMc + p))*NAc + sa) * 3;
        const float l0 = __ldg(lp), l1 = __ldg(lp + 1), l2 = __ldg(lp + 2);

        // ---- mma1: 32 fp16 mma/warp, 2 LDS.128 per kstep ----
        float D[4][4];
        #pragma unroll
        for (int n = 0; n < 4; ++n) { D[n][0]=0.f; D[n][1]=0.f; D[n][2]=0.f; D[n][3]=0.f; }
        #pragma unroll
        for (int kk = 0; kk < 8; ++kk) {
            const uint4 v0 = *(const uint4*)(xb + (8*kk + t4    ) * XHS + 32*wN + 4*g8);
            const uint4 v1 = *(const uint4*)(xb + (8*kk + t4 + 4) * XHS + 32*wN + 4*g8);
            mma_f16(D[0], A[4*kk], A[4*kk+1], A[4*kk+2], A[4*kk+3], v0.x, v1.x);
            mma_f16(D[1], A[4*kk], A[4*kk+1], A[4*kk+2], A[4*kk+3], v0.y, v1.y);
            mma_f16(D[2], A[4*kk], A[4*kk+1], A[4*kk+2], A[4*kk+3], v0.z, v1.z);
            mma_f16(D[3], A[4*kk], A[4*kk+1], A[4*kk+2], A[4*kk+3], v0.w, v1.w);
        }

        // ---- prefetch group g+1's X into registers (issued post-mma1 so the
        //      q regs don't overlap the mma1-hot window; ~1000+ cyc to use) ----
        float4 q0a, q0b, q1a, q1b, q2a, q2b, q3a, q3b;
        if (g + 1 < GRPS) {
            const int gp1 = gp + 1;
            const int b1 = gp1 >> 10, p1 = gp1 & 1023;
            const float* fb1 = feat + (size_t)b1 * FDc * cs + (size_t)p1 * NAc;
            q0a = __ldg((const float4*)(fb1 + (size_t)(2*cp0      ) * cs) + ab);
            q0b = __ldg((const float4*)(fb1 + (size_t)(2*cp0 +  1) * cs) + ab);
            q1a = __ldg((const float4*)(fb1 + (size_t)(2*cp0 + 32) * cs) + ab);
            q1b = __ldg((const float4*)(fb1 + (size_t)(2*cp0 + 33) * cs) + ab);
            q2a = __ldg((const float4*)(fb1 + (size_t)(2*cp0 + 64) * cs) + ab);
            q2b = __ldg((const float4*)(fb1 + (size_t)(2*cp0 + 65) * cs) + ab);
            q3a = __ldg((const float4*)(fb1 + (size_t)(2*cp0 + 96) * cs) + ab);
            q3b = __ldg((const float4*)(fb1 + (size_t)(2*cp0 + 97) * cs) + ab);
        }

        // ---- spatial branch -> C k-pairs 32..39 ----
        {
            float s1v[8];
            #pragma unroll
            for (int j = 0; j < 8; ++j)
                s1v[j] = tanha(sB1[j][0]*l0 + sB1[j][1]*l1 + sB1[j][2]*l2 + sd1[j]);
            float acc0 = sd2[4*sos+0], acc1 = sd2[4*sos+1];
            float acc2 = sd2[4*sos+2], acc3 = sd2[4*sos+3];
            #pragma unroll
            for (int i = 0; i < 8; ++i) {
                acc0 += sB2[4*sos+0][i] * s1v[i];
                acc1 += sB2[4*sos+1][i] * s1v[i];
                acc2 += sB2[4*sos+2][i] * s1v[i];
                acc3 += sB2[4*sos+3][i] * s1v[i];
            }
            sCH[(32 + 2*sos) * CHS + sa] = pkh2(tanha(acc0), tanha(acc1));
            sCH[(33 + 2*sos) * CHS + sa] = pkh2(tanha(acc2), tanha(acc3));
        }

        // ---- epi1: tanh(H + c1) -> C k-pairs 0..31 (2 STS.128) ----
        {
            const int pp = 8*wM + g8;
            const float c1a = sc1[16*wM + g8];
            const float c1b = sc1[16*wM + g8 + 8];
            u32* cw = sCH + pp * CHS + 32*wN + 8*t4;
            uint4 w;
            w.x = pkh2(tanha(D[0][0] + c1a), tanha(D[0][2] + c1b));
            w.y = pkh2(tanha(D[1][0] + c1a), tanha(D[1][2] + c1b));
            w.z = pkh2(tanha(D[2][0] + c1a), tanha(D[2][2] + c1b));
            w.w = pkh2(tanha(D[3][0] + c1a), tanha(D[3][2] + c1b));
            *(uint4*)cw = w;
            w.x = pkh2(tanha(D[0][1] + c1a), tanha(D[0][3] + c1b));
            w.y = pkh2(tanha(D[1][1] + c1a), tanha(D[1][3] + c1b));
            w.z = pkh2(tanha(D[2][1] + c1a), tanha(D[2][3] + c1b));
            w.w = pkh2(tanha(D[3][1] + c1a), tanha(D[3][3] + c1b));
            *(uint4*)(cw + 4) = w;
        }
        __syncthreads();            // sC ready; xb reads done

        // ---- mma2: 10 fp16 mma/warp, M2 frags in registers ----
        float D2[2][4];
        D2[0][0]=0.f; D2[0][1]=0.f; D2[0][2]=0.f; D2[0][3]=0.f;
        D2[1][0]=0.f; D2[1][1]=0.f; D2[1][2]=0.f; D2[1][3]=0.f;
        #pragma unroll
        for (int kk2 = 0; kk2 < 5; ++kk2) {
            const uint2 w0 = *(const uint2*)(sCH + (8*kk2 + t4    ) * CHS + 16*nt + 2*g8);
            const uint2 w1 = *(const uint2*)(sCH + (8*kk2 + t4 + 4) * CHS + 16*nt + 2*g8);
            mma_f16(D2[0], M[4*kk2], M[4*kk2+1], M[4*kk2+2], M[4*kk2+3], w0.x, w1.x);
            mma_f16(D2[1], M[4*kk2], M[4*kk2+1], M[4*kk2+2], M[4*kk2+3], w0.y, w1.y);
        }

        // ---- epi2: head partials; D2[n2] col 2t4+s -> anchor 16nt+4t4+2s+n2 ----
        {
            const int ro = 16*m + g8;
            const float wa  = sWa2v[ro],   wb  = sWa2v[ro + 8];
            const float caa = sca[ro],     cab = sca[ro + 8];
            float p0 = wa * tanhp(D2[0][0] + caa) + wb * tanhp(D2[0][2] + cab); // +0
            float p2 = wa * tanhp(D2[1][0] + caa) + wb * tanhp(D2[1][2] + cab); // +1
            float p1 = wa * tanhp(D2[0][1] + caa) + wb * tanhp(D2[0][3] + cab); // +2
            float p3 = wa * tanhp(D2[1][1] + caa) + wb * tanhp(D2[1][3] + cab); // +3
            const unsigned m32 = 0xffffffffu;
            #pragma unroll
            for (int off = 4; off <= 16; off <<= 1) {
                p0 += __shfl_xor_sync(m32, p0, off);
                p1 += __shfl_xor_sync(m32, p1, off);
                p2 += __shfl_xor_sync(m32, p2, off);
                p3 += __shfl_xor_sync(m32, p3, off);
            }
            if (g8 == 0) {
                float4 v; v.x = p0; v.y = p2; v.z = p1; v.w = p3;
                *(float4*)&sPart[g & 1][m][16*nt + 4*t4] = v;
            }
        }

        // ---- convert + store X[g+1] (LDG latency fully elapsed by now) ----
        if (g + 1 < GRPS) {
            u32* xd = sXH + ((g + 1) & 1) * (64 * XHS);
            uint4 w;
            w.x = pkh2(q0a.x, q0b.x); w.y = pkh2(q0a.y, q0b.y);
            w.z = pkh2(q0a.z, q0b.z); w.w = pkh2(q0a.w, q0b.w);
            *(uint4*)(xd + (cp0     ) * XHS + 4 * ab) = w;
            w.x = pkh2(q1a.x, q1b.x); w.y = pkh2(q1a.y, q1b.y);
            w.z = pkh2(q1a.z, q1b.z); w.w = pkh2(q1a.w, q1b.w);
            *(uint4*)(xd + (cp0 + 16) * XHS + 4 * ab) = w;
            w.x = pkh2(q2a.x, q2b.x); w.y = pkh2(q2a.y, q2b.y);
            w.z = pkh2(q2a.z, q2b.z); w.w = pkh2(q2a.w, q2b.w);
            *(uint4*)(xd + (cp0 + 32) * XHS + 4 * ab) = w;
            w.x = pkh2(q3a.x, q3b.x); w.y = pkh2(q3a.y, q3b.y);
            w.z = pkh2(q3a.z, q3b.z); w.w = pkh2(q3a.w, q3b.w);
            *(uint4*)(xd + (cp0 + 48) * XHS + 4 * ab) = w;
        }
        __syncthreads();            // sPart + X[g+1] visible; sC reads done

        // ---- tail: warp 0 softmax + min-max norm (overlaps next mma1) ----
        if (warp == 0) {
            const int a0 = lane, a1 = lane + 32;
            const float* pb0 = sPart[g & 1][0];
            const float* pb1 = sPart[g & 1][1];
            const float lg0 = tanhp(pb0[a0] + pb1[a0] + sba2[0]);
            const float lg1 = tanhp(pb0[a1] + pb1[a1] + sba2[0]);

            const unsigned m32 = 0xffffffffu;
            float mx = fmaxf(lg0, lg1);
            float mn = fminf(lg0, lg1);
            #pragma unroll
            for (int off = 16; off > 0; off >>= 1) {
                mx = fmaxf(mx, __shfl_xor_sync(m32, mx, off));
                mn = fminf(mn, __shfl_xor_sync(m32, mn, off));
            }
            const float e0 = expf(lg0 - mx);
            const float e1 = expf(lg1 - mx);
            float ssum = e0 + e1;
            #pragma unroll
            for (int off = 16; off > 0; off >>= 1) ssum += __shfl_xor_sync(m32, ssum, off);
            const float invs = 1.0f / ssum;

            const float w0  = e0 * invs;
            const float w1  = e1 * invs;
            const float wmn = expf(mn - mx) * invs;
            const float wmx = invs;
            const float kk  = (1.0f + 1e-6f) / (wmx - wmn + 1e-6f);

            float* ob = out + (size_t)gp * NAc;
            float* on = ob + (size_t)BZc * NUMc * NAc;
            ob[a0] = w0;
            ob[a1] = w1;
            on[a0] = kk * (w0 - wmn);
            on[a1] = kk * (w1 - wmn);
        }
    }
}

// ---------------- launch ----------------
extern "C" void kernel_launch(void* const* d_in, const int* in_sizes, int n_in,
                              void* d_out, int out_size)
{
    const float* loc  = (const float*)d_in[0];
    const float* feat = (const float*)d_in[1];

    disarm_prep<<<1, 256>>>(
        (const float*)d_in[2],  (const float*)d_in[3],  (const float*)d_in[4],  (const float*)d_in[5],
        (const float*)d_in[6],  (const float*)d_in[7],
        (const float*)d_in[8],  (const float*)d_in[9],  (const float*)d_in[10], (const float*)d_in[11],
        (const float*)d_in[12], (const float*)d_in[13], (const float*)d_in[14], (const float*)d_in[15],
        (const float*)d_in[16], (const float*)d_in[17],
        (const float*)d_in[18], (const float*)d_in[19], (const float*)d_in[20], (const float*)d_in[21],
        (const float*)d_in[22], (const float*)d_in[23]);

    static int smem_set = 0;
    if (!smem_set) {
        cudaFuncSetAttribute(disarm_mma,
                             cudaFuncAttributeMaxDynamicSharedMemorySize, SM_TOTAL);
        smem_set = 1;
    }
    disarm_mma<<<(BZc * NUMc) / GRPS, 256, SM_TOTAL>>>(loc, feat, (float*)d_out);
}

// round 12
// speedup vs baseline: 1.2618x; 1.0730x over previous
#include <cuda_runtime.h>
#include <cuda_fp16.h>
#include <cstdint>

// Problem dims
#define BZc   8
#define NUMc  1024
#define NAc   64
#define FDc   128
#define GRPS  8          // (b,p) groups per CTA

typedef unsigned int u32;

// ---------------- helpers ----------------
__device__ __forceinline__ float tanha(float x) {           // HW approx
    float y; asm("tanh.approx.f32 %0, %1;" : "=f"(y) : "f"(x)); return y;
}
// Fast precise tanh: ex2 + rcp + 1 Newton step (~4e-7). Final logit only.
__device__ __forceinline__ float tanhp(float x) {
    float t; asm("ex2.approx.f32 %0, %1;" : "=f"(t) : "f"(x * 2.8853900817779268f));
    float d = 1.0f + t;
    float r; asm("rcp.approx.f32 %0, %1;" : "=f"(r) : "f"(d));
    r = fmaf(fmaf(-d, r, 1.0f), r, r);
    return fmaf(-2.0f, r, 1.0f);
}
__device__ __forceinline__ u32 pkh2(float a, float b) {
    __half2 h = __floats2half2_rn(a, b);
    return *(u32*)&h;
}
__device__ __forceinline__ void mma_f16(float d[4],
    u32 a0, u32 a1, u32 a2, u32 a3, u32 b0, u32 b1)
{
    asm("mma.sync.aligned.m16n8k16.row.col.f32.f16.f16.f32 "
        "{%0,%1,%2,%3}, {%4,%5,%6,%7}, {%8,%9}, {%0,%1,%2,%3};"
        : "+f"(d[0]), "+f"(d[1]), "+f"(d[2]), "+f"(d[3])
        : "r"(a0), "r"(a1), "r"(a2), "r"(a3), "r"(b0), "r"(b1));
}

// ---------------- folded weight storage (fp16 fragment layouts) ----------------
__device__ uint4 g_WhF[4 * 8 * 32];   // A1 frags [tile(4)][kk(8)][lane(32)]
__device__ uint4 g_M2hF[2 * 5 * 32];  // M2 frags [m(2)][kk2(5)][lane(32)]
__device__ float g_c1[64];
__device__ float g_ca[32];
__device__ float g_B1[8][4];
__device__ float g_d1[8];
__device__ float g_B2[16][8];
__device__ float g_d2[16];
__device__ float g_Wa2[32];
__device__ float g_ba2s;

// ---------------- weight folding kernel (multi-block grid-stride) ----------------
__global__ void disarm_prep(
    const float* __restrict__ Wf1, const float* __restrict__ bf1,
    const float* __restrict__ gf1, const float* __restrict__ btf1,
    const float* __restrict__ Wf2, const float* __restrict__ bf2,
    const float* __restrict__ Ws1, const float* __restrict__ bs1,
    const float* __restrict__ gs1, const float* __restrict__ bts1,
    const float* __restrict__ Ws2, const float* __restrict__ bs2,
    const float* __restrict__ gs2, const float* __restrict__ bts2,
    const float* __restrict__ Ws3, const float* __restrict__ bs3,
    const float* __restrict__ Wa1, const float* __restrict__ ba1,
    const float* __restrict__ ga1, const float* __restrict__ bta1,
    const float* __restrict__ Wa2, const float* __restrict__ ba2)
{
    const float inv = rsqrtf(1.0f + 1e-5f);
    const int t  = threadIdx.x + blockIdx.x * blockDim.x;
    const int nt = blockDim.x * gridDim.x;
    const int lt = threadIdx.x;

    auto wt = [&](int r, int c) -> float {
        return gf1[r] * inv * Wf1[r * FDc + c];
    };
    for (int i = t; i < 4 * 8 * 32; i += nt) {
        int tile = i >> 8, kk = (i >> 5) & 7, lane = i & 31;
        int g8 = lane >> 2, t4 = lane & 3;
        int r = 16 * tile + g8, c = 16 * kk + 2 * t4;
        uint4 v;
        v.x = pkh2(wt(r,     c), wt(r,     c + 1));
        v.y = pkh2(wt(r + 8, c), wt(r + 8, c + 1));
        v.z = pkh2(wt(r,     c + 8), wt(r,     c + 9));
        v.w = pkh2(wt(r + 8, c + 8), wt(r + 8, c + 9));
        g_WhF[i] = v;
    }
    auto m2 = [&](int o, int kk) -> float {
        float acc = 0.0f;
        if (kk < 64) {
            for (int j = 0; j < 32; ++j) acc += Wa1[o*64 + 32 + j] * Wf2[j*64 + kk];
        } else {
            for (int mq = 0; mq < 32; ++mq) acc += Wa1[o*64 + mq] * Ws3[mq*16 + (kk - 64)];
        }
        return ga1[o] * inv * acc;
    };
    // k-pair unit map: pair p<32 -> hidden rows (16(p>>3)+(p&7)), +8;
    //                  p>=32 -> spatial units 2(p-32), +1
    auto U = [&](int p, int e) -> int {
        if (p < 32) return 16 * (p >> 3) + (p & 7) + 8 * e;
        return 64 + 2 * (p - 32) + e;
    };
    for (int i = t; i < 2 * 5 * 32; i += nt) {
        int m = i / (5 * 32), kk2 = (i / 32) % 5, lane = i & 31;
        int g8 = lane >> 2, t4 = lane & 3;
        int r = 16 * m + g8;
        int p = 8 * kk2 + t4;
        uint4 v;
        v.x = pkh2(m2(r,     U(p, 0)),     m2(r,     U(p, 1)));
        v.y = pkh2(m2(r + 8, U(p, 0)),     m2(r + 8, U(p, 1)));
        v.z = pkh2(m2(r,     U(p + 4, 0)), m2(r,     U(p + 4, 1)));
        v.w = pkh2(m2(r + 8, U(p + 4, 0)), m2(r + 8, U(p + 4, 1)));
        g_M2hF[i] = v;
    }
    if (blockIdx.x == 0) {
        for (int i = lt; i < 64; i += blockDim.x) g_c1[i] = gf1[i]*inv*bf1[i] + btf1[i];
        if (lt < 32) {
            float acc = 0.0f;
            for (int j = 0; j < 32; ++j) acc += Wa1[lt*64 + 32 + j] * bf2[j];
            for (int mq = 0; mq < 32; ++mq) acc += Wa1[lt*64 + mq] * bs3[mq];
            g_ca[lt] = ga1[lt]*inv*(acc + ba1[lt]) + bta1[lt];
        }
        if (lt < 8) {
            for (int i = 0; i < 3; ++i) g_B1[lt][i] = gs1[lt]*inv*Ws1[lt*3 + i];
            g_B1[lt][3] = 0.0f;
            g_d1[lt] = gs1[lt]*inv*bs1[lt] + bts1[lt];
        }
        if (lt < 16) {
            for (int i = 0; i < 8; ++i) g_B2[lt][i] = gs2[lt]*inv*Ws2[lt*8 + i];
            g_d2[lt] = gs2[lt]*inv*bs2[lt] + bts2[lt];
        }
        if (lt < 32) g_Wa2[lt] = Wa2[lt];
        if (lt == 0) g_ba2s = ba2[0];
    }
}

// ---------------- smem layout (bytes) ----------------
#define XHS      72                         // u32 per channel-pair row
#define XHBUF    (64 * XHS * 4)             // 18432 B
#define CHS      72
#define SM_XH    0                          // 2 buffers: 36864
#define SM_CH    (2 * XHBUF)                // 40*72*4 = 11520
#define SM_PART  (SM_CH + 11520)            // 2 bufs * 2 * 64 * 4 = 1024
#define SM_C1    (SM_PART + 1024)           // 256
#define SM_CA    (SM_C1 + 256)              // 128
#define SM_WA2   (SM_CA + 128)              // 128
#define SM_B1    (SM_WA2 + 128)             // 128
#define SM_D1    (SM_B1 + 128)              // 32
#define SM_B2    (SM_D1 + 32)               // 512
#define SM_D2    (SM_B2 + 512)              // 64
#define SM_BA2   (SM_D2 + 64)               // 16
#define SM_TOTAL (SM_BA2 + 16)

// ---------------- main fused kernel ----------------
// Round-11 structure exactly; epi2 head tanh switched tanhp->tanha (error
// enters a 32-term weighted sum, |Wa2|~0.05 -> logit noise ~1.4e-4).
__global__ void __launch_bounds__(256, 2) disarm_mma(
    const float* __restrict__ loc, const float* __restrict__ feat,
    float* __restrict__ out)
{
    extern __shared__ char smem[];
    u32* sXH = (u32*)(smem + SM_XH);
    u32* sCH = (u32*)(smem + SM_CH);
    float (*sPart)[2][64] = (float (*)[2][64])(smem + SM_PART);  // [buf][m][a]
    float* sc1   = (float*)(smem + SM_C1);
    float* sca   = (float*)(smem + SM_CA);
    float* sWa2v = (float*)(smem + SM_WA2);
    float (*sB1)[4] = (float (*)[4])(smem + SM_B1);
    float* sd1   = (float*)(smem + SM_D1);
    float (*sB2)[8] = (float (*)[8])(smem + SM_B2);
    float* sd2   = (float*)(smem + SM_D2);
    float* sba2  = (float*)(smem + SM_BA2);

    const int tid  = threadIdx.x;
    const int warp = tid >> 5;
    const int lane = tid & 31;
    const int g8   = lane >> 2;
    const int t4   = lane & 3;
    const int wM   = warp >> 1;   // mma1 row tile (0..3)
    const int wN   = warp & 1;    // mma1 anchor half (0..1)
    const int m    = warp & 1;    // mma2 row half
    const int nt   = warp >> 1;   // mma2 anchor 16-col tile

    const size_t cs = (size_t)NUMc * NAc;
    const int gp0 = blockIdx.x * GRPS;

    // X-staging indices (iteration-invariant parts folded to scalars)
    const int cp0 = tid >> 4;      // channel-pair base; iter it uses cp0 + 16*it
    const int ab  = tid & 15;      // anchor block (same for all it)

    // ---- persistent A1 fragments (8 coalesced LDG.128) ----
    u32 A[32];
    {
        const uint4* aw = g_WhF + (size_t)wM * 8 * 32 + lane;
        #pragma unroll
        for (int kk = 0; kk < 8; ++kk) {
            uint4 v = __ldg(aw + kk * 32);
            A[4*kk+0] = v.x; A[4*kk+1] = v.y; A[4*kk+2] = v.z; A[4*kk+3] = v.w;
        }
    }
    // ---- persistent M2 fragments (5 coalesced LDG.128) ----
    u32 M[20];
    {
        const uint4* mw = g_M2hF + (size_t)m * 5 * 32 + lane;
        #pragma unroll
        for (int kk2 = 0; kk2 < 5; ++kk2) {
            uint4 v = __ldg(mw + kk2 * 32);
            M[4*kk2+0] = v.x; M[4*kk2+1] = v.y; M[4*kk2+2] = v.z; M[4*kk2+3] = v.w;
        }
    }

    // ---- stage small weights ----
    if (tid < 64) sc1[tid] = g_c1[tid];
    if (tid < 32) { sca[tid] = g_ca[tid]; sWa2v[tid] = g_Wa2[tid]; }
    if (tid < 32) sB1[tid>>2][tid&3] = g_B1[tid>>2][tid&3];
    if (tid < 8)  sd1[tid] = g_d1[tid];
    if (tid >= 128 && tid < 256) sB2[(tid-128)>>3][(tid-128)&7] = g_B2[(tid-128)>>3][(tid-128)&7];
    if (tid < 16) sd2[tid] = g_d2[tid];
    if (tid == 0) sba2[0] = g_ba2s;

    // ---- prologue: fill X half tile for group 0 ----
    {
        const int b = gp0 >> 10, p = gp0 & 1023;
        const float* fb = feat + (size_t)b * FDc * cs + (size_t)p * NAc;
        #pragma unroll
        for (int it = 0; it < 4; ++it) {
            const int cp = cp0 + 16 * it;
            float4 xa = __ldg((const float4*)(fb + (size_t)(2*cp  ) * cs) + ab);
            float4 xc = __ldg((const float4*)(fb + (size_t)(2*cp+1) * cs) + ab);
            uint4 w;
            w.x = pkh2(xa.x, xc.x); w.y = pkh2(xa.y, xc.y);
            w.z = pkh2(xa.z, xc.z); w.w = pkh2(xa.w, xc.w);
            *(uint4*)(sXH + cp * XHS + 4 * ab) = w;
        }
    }
    __syncthreads();

    const int sa  = tid & 63;       // spatial anchor
    const int sos = tid >> 6;       // spatial output slice (4 outputs)

    #pragma unroll 1
    for (int g = 0; g < GRPS; ++g) {
        const int gp = gp0 + g;
        const int b  = gp >> 10;
        const int p  = gp & 1023;
        u32* xb = sXH + (g & 1) * (64 * XHS);

        // early loc load (latency hides under mma1)
        const float* lp = loc + (((size_t)(b*NUMc + p))*NAc + sa) * 3;
        const float l0 = __ldg(lp), l1 = __ldg(lp + 1), l2 = __ldg(lp + 2);

        // ---- mma1: 32 fp16 mma/warp, 2 LDS.128 per kstep ----
        float D[4][4];
        #pragma unroll
        for (int n = 0; n < 4; ++n) { D[n][0]=0.f; D[n][1]=0.f; D[n][2]=0.f; D[n][3]=0.f; }
        #pragma unroll
        for (int kk = 0; kk < 8; ++kk) {
            const uint4 v0 = *(const uint4*)(xb + (8*kk + t4    ) * XHS + 32*wN + 4*g8);
            const uint4 v1 = *(const uint4*)(xb + (8*kk + t4 + 4) * XHS + 32*wN + 4*g8);
            mma_f16(D[0], A[4*kk], A[4*kk+1], A[4*kk+2], A[4*kk+3], v0.x, v1.x);
            mma_f16(D[1], A[4*kk], A[4*kk+1], A[4*kk+2], A[4*kk+3], v0.y, v1.y);
            mma_f16(D[2], A[4*kk], A[4*kk+1], A[4*kk+2], A[4*kk+3], v0.z, v1.z);
            mma_f16(D[3], A[4*kk], A[4*kk+1], A[4*kk+2], A[4*kk+3], v0.w, v1.w);
        }

        // ---- prefetch group g+1's X into registers (post-mma1: q regs do not
        //      overlap the mma1-hot window; ~1000+ cyc until consumption) ----
        float4 q0a, q0b, q1a, q1b, q2a, q2b, q3a, q3b;
        if (g + 1 < GRPS) {
            const int gp1 = gp + 1;
            const int b1 = gp1 >> 10, p1 = gp1 & 1023;
            const float* fb1 = feat + (size_t)b1 * FDc * cs + (size_t)p1 * NAc;
            q0a = __ldg((const float4*)(fb1 + (size_t)(2*cp0      ) * cs) + ab);
            q0b = __ldg((const float4*)(fb1 + (size_t)(2*cp0 +  1) * cs) + ab);
            q1a = __ldg((const float4*)(fb1 + (size_t)(2*cp0 + 32) * cs) + ab);
            q1b = __ldg((const float4*)(fb1 + (size_t)(2*cp0 + 33) * cs) + ab);
            q2a = __ldg((const float4*)(fb1 + (size_t)(2*cp0 + 64) * cs) + ab);
            q2b = __ldg((const float4*)(fb1 + (size_t)(2*cp0 + 65) * cs) + ab);
            q3a = __ldg((const float4*)(fb1 + (size_t)(2*cp0 + 96) * cs) + ab);
            q3b = __ldg((const float4*)(fb1 + (size_t)(2*cp0 + 97) * cs) + ab);
        }

        // ---- spatial branch -> C k-pairs 32..39 ----
        {
            float s1v[8];
            #pragma unroll
            for (int j = 0; j < 8; ++j)
                s1v[j] = tanha(sB1[j][0]*l0 + sB1[j][1]*l1 + sB1[j][2]*l2 + sd1[j]);
            float acc0 = sd2[4*sos+0], acc1 = sd2[4*sos+1];
            float acc2 = sd2[4*sos+2], acc3 = sd2[4*sos+3];
            #pragma unroll
            for (int i = 0; i < 8; ++i) {
                acc0 += sB2[4*sos+0][i] * s1v[i];
                acc1 += sB2[4*sos+1][i] * s1v[i];
                acc2 += sB2[4*sos+2][i] * s1v[i];
                acc3 += sB2[4*sos+3][i] * s1v[i];
            }
            sCH[(32 + 2*sos) * CHS + sa] = pkh2(tanha(acc0), tanha(acc1));
            sCH[(33 + 2*sos) * CHS + sa] = pkh2(tanha(acc2), tanha(acc3));
        }

        // ---- epi1: tanh(H + c1) -> C k-pairs 0..31 (2 STS.128) ----
        {
            const int pp = 8*wM + g8;
            const float c1a = sc1[16*wM + g8];
            const float c1b = sc1[16*wM + g8 + 8];
            u32* cw = sCH + pp * CHS + 32*wN + 8*t4;
            uint4 w;
            w.x = pkh2(tanha(D[0][0] + c1a), tanha(D[0][2] + c1b));
            w.y = pkh2(tanha(D[1][0] + c1a), tanha(D[1][2] + c1b));
            w.z = pkh2(tanha(D[2][0] + c1a), tanha(D[2][2] + c1b));
            w.w = pkh2(tanha(D[3][0] + c1a), tanha(D[3][2] + c1b));
            *(uint4*)cw = w;
            w.x = pkh2(tanha(D[0][1] + c1a), tanha(D[0][3] + c1b));
            w.y = pkh2(tanha(D[1][1] + c1a), tanha(D[1][3] + c1b));
            w.z = pkh2(tanha(D[2][1] + c1a), tanha(D[2][3] + c1b));
            w.w = pkh2(tanha(D[3][1] + c1a), tanha(D[3][3] + c1b));
            *(uint4*)(cw + 4) = w;
        }
        __syncthreads();            // sC ready; xb reads done

        // ---- mma2: 10 fp16 mma/warp, M2 frags in registers ----
        float D2[2][4];
        D2[0][0]=0.f; D2[0][1]=0.f; D2[0][2]=0.f; D2[0][3]=0.f;
        D2[1][0]=0.f; D2[1][1]=0.f; D2[1][2]=0.f; D2[1][3]=0.f;
        #pragma unroll
        for (int kk2 = 0; kk2 < 5; ++kk2) {
            const uint2 w0 = *(const uint2*)(sCH + (8*kk2 + t4    ) * CHS + 16*nt + 2*g8);
            const uint2 w1 = *(const uint2*)(sCH + (8*kk2 + t4 + 4) * CHS + 16*nt + 2*g8);
            mma_f16(D2[0], M[4*kk2], M[4*kk2+1], M[4*kk2+2], M[4*kk2+3], w0.x, w1.x);
            mma_f16(D2[1], M[4*kk2], M[4*kk2+1], M[4*kk2+2], M[4*kk2+3], w0.y, w1.y);
        }

        // ---- epi2: head partials (HW tanh — noise attenuated by Wa2 sum) ----
        {
            const int ro = 16*m + g8;
            const float wa  = sWa2v[ro],   wb  = sWa2v[ro + 8];
            const float caa = sca[ro],     cab = sca[ro + 8];
            float p0 = wa * tanha(D2[0][0] + caa) + wb * tanha(D2[0][2] + cab); // +0
            float p2 = wa * tanha(D2[1][0] + caa) + wb * tanha(D2[1][2] + cab); // +1
            float p1 = wa * tanha(D2[0][1] + caa) + wb * tanha(D2[0][3] + cab); // +2
            float p3 = wa * tanha(D2[1][1] + caa) + wb * tanha(D2[1][3] + cab); // +3
            const unsigned m32 = 0xffffffffu;
            #pragma unroll
            for (int off = 4; off <= 16; off <<= 1) {
                p0 += __shfl_xor_sync(m32, p0, off);
                p1 += __shfl_xor_sync(m32, p1, off);
                p2 += __shfl_xor_sync(m32, p2, off);
                p3 += __shfl_xor_sync(m32, p3, off);
            }
            if (g8 == 0) {
                float4 v; v.x = p0; v.y = p2; v.z = p1; v.w = p3;
                *(float4*)&sPart[g & 1][m][16*nt + 4*t4] = v;
            }
        }

        // ---- convert + store X[g+1] (LDG latency fully elapsed by now) ----
        if (g + 1 < GRPS) {
            u32* xd = sXH + ((g + 1) & 1) * (64 * XHS);
            uint4 w;
            w.x = pkh2(q0a.x, q0b.x); w.y = pkh2(q0a.y, q0b.y);
            w.z = pkh2(q0a.z, q0b.z); w.w = pkh2(q0a.w, q0b.w);
            *(uint4*)(xd + (cp0     ) * XHS + 4 * ab) = w;
            w.x = pkh2(q1a.x, q1b.x); w.y = pkh2(q1a.y, q1b.y);
            w.z = pkh2(q1a.z, q1b.z); w.w = pkh2(q1a.w, q1b.w);
            *(uint4*)(xd + (cp0 + 16) * XHS + 4 * ab) = w;
            w.x = pkh2(q2a.x, q2b.x); w.y = pkh2(q2a.y, q2b.y);
            w.z = pkh2(q2a.z, q2b.z); w.w = pkh2(q2a.w, q2b.w);
            *(uint4*)(xd + (cp0 + 32) * XHS + 4 * ab) = w;
            w.x = pkh2(q3a.x, q3b.x); w.y = pkh2(q3a.y, q3b.y);
            w.z = pkh2(q3a.z, q3b.z); w.w = pkh2(q3a.w, q3b.w);
            *(uint4*)(xd + (cp0 + 48) * XHS + 4 * ab) = w;
        }
        __syncthreads();            // sPart + X[g+1] visible; sC reads done

        // ---- tail: warp 0 softmax + min-max norm (overlaps next mma1) ----
        if (warp == 0) {
            const int a0 = lane, a1 = lane + 32;
            const float* pb0 = sPart[g & 1][0];
            const float* pb1 = sPart[g & 1][1];
            const float lg0 = tanhp(pb0[a0] + pb1[a0] + sba2[0]);
            const float lg1 = tanhp(pb0[a1] + pb1[a1] + sba2[0]);

            const unsigned m32 = 0xffffffffu;
            float mx = fmaxf(lg0, lg1);
            float mn = fminf(lg0, lg1);
            #pragma unroll
            for (int off = 16; off > 0; off >>= 1) {
                mx = fmaxf(mx, __shfl_xor_sync(m32, mx, off));
                mn = fminf(mn, __shfl_xor_sync(m32, mn, off));
            }
            const float e0 = expf(lg0 - mx);
            const float e1 = expf(lg1 - mx);
            float ssum = e0 + e1;
            #pragma unroll
            for (int off = 16; off > 0; off >>= 1) ssum += __shfl_xor_sync(m32, ssum, off);
            const float invs = 1.0f / ssum;

            const float w0  = e0 * invs;
            const float w1  = e1 * invs;
            const float wmn = expf(mn - mx) * invs;
            const float wmx = invs;
            const float kk  = (1.0f + 1e-6f) / (wmx - wmn + 1e-6f);

            float* ob = out + (size_t)gp * NAc;
            float* on = ob + (size_t)BZc * NUMc * NAc;
            ob[a0] = w0;
            ob[a1] = w1;
            on[a0] = kk * (w0 - wmn);
            on[a1] = kk * (w1 - wmn);
        }
    }
}

// ---------------- launch ----------------
extern "C" void kernel_launch(void* const* d_in, const int* in_sizes, int n_in,
                              void* d_out, int out_size)
{
    const float* loc  = (const float*)d_in[0];
    const float* feat = (const float*)d_in[1];

    disarm_prep<<<16, 256>>>(
        (const float*)d_in[2],  (const float*)d_in[3],  (const float*)d_in[4],  (const float*)d_in[5],
        (const float*)d_in[6],  (const float*)d_in[7],
        (const float*)d_in[8],  (const float*)d_in[9],  (const float*)d_in[10], (const float*)d_in[11],
        (const float*)d_in[12], (const float*)d_in[13], (const float*)d_in[14], (const float*)d_in[15],
        (const float*)d_in[16], (const float*)d_in[17],
        (const float*)d_in[18], (const float*)d_in[19], (const float*)d_in[20], (const float*)d_in[21],
        (const float*)d_in[22], (const float*)d_in[23]);

    static int smem_set = 0;
    if (!smem_set) {
        cudaFuncSetAttribute(disarm_mma,
                             cudaFuncAttributeMaxDynamicSharedMemorySize, SM_TOTAL);
        smem_set = 1;
    }
    disarm_mma<<<(BZc * NUMc) / GRPS, 256, SM_TOTAL>>>(loc, feat, (float*)d_out);
}

// round 13
// speedup vs baseline: 1.3632x; 1.0804x over previous
#include <cuda_runtime.h>
#include <cuda_fp16.h>
#include <cstdint>

// Problem dims
#define BZc   8
#define NUMc  1024
#define NAc   64
#define FDc   128
#define GRPS  8          // (b,p) groups per CTA

typedef unsigned int u32;
typedef unsigned long long u64;

// ---------------- helpers ----------------
__device__ __forceinline__ float tanha(float x) {           // HW approx
    float y; asm("tanh.approx.f32 %0, %1;" : "=f"(y) : "f"(x)); return y;
}
// Fast precise tanh: ex2 + rcp + 1 Newton step (~4e-7). Final logit only.
__device__ __forceinline__ float tanhp(float x) {
    float t; asm("ex2.approx.f32 %0, %1;" : "=f"(t) : "f"(x * 2.8853900817779268f));
    float d = 1.0f + t;
    float r; asm("rcp.approx.f32 %0, %1;" : "=f"(r) : "f"(d));
    r = fmaf(fmaf(-d, r, 1.0f), r, r);
    return fmaf(-2.0f, r, 1.0f);
}
__device__ __forceinline__ u32 pkh2(float a, float b) {
    __half2 h = __floats2half2_rn(a, b);
    return *(u32*)&h;
}
__device__ __forceinline__ u64 pk2(float a, float b) {
    u64 r; asm("mov.b64 %0, {%1,%2};" : "=l"(r) : "f"(a), "f"(b)); return r;
}
__device__ __forceinline__ void upk2(u64 v, float& a, float& b) {
    asm("mov.b64 {%0,%1}, %2;" : "=f"(a), "=f"(b) : "l"(v));
}
__device__ __forceinline__ u64 ffma2(u64 a, u64 b, u64 c) {
    u64 d; asm("fma.rn.f32x2 %0, %1, %2, %3;" : "=l"(d) : "l"(a), "l"(b), "l"(c)); return d;
}
__device__ __forceinline__ void mma_f16(float d[4],
    u32 a0, u32 a1, u32 a2, u32 a3, u32 b0, u32 b1)
{
    asm("mma.sync.aligned.m16n8k16.row.col.f32.f16.f16.f32 "
        "{%0,%1,%2,%3}, {%4,%5,%6,%7}, {%8,%9}, {%0,%1,%2,%3};"
        : "+f"(d[0]), "+f"(d[1]), "+f"(d[2]), "+f"(d[3])
        : "r"(a0), "r"(a1), "r"(a2), "r"(a3), "r"(b0), "r"(b1));
}

// ---------------- folded weight storage (fp16 fragment layouts) ----------------
__device__ uint4 g_WhF[4 * 8 * 32];   // A1 frags [tile(4)][kk(8)][lane(32)]
__device__ uint4 g_M2hF[2 * 5 * 32];  // M2 frags [m(2)][kk2(5)][lane(32)]
__device__ float g_c1[64];
__device__ float g_ca[32];
__device__ float g_B1[8][4];
__device__ float g_d1[8];
__device__ u64   g_B2p[8][8];         // packed output-pairs of folded Ws2
__device__ u64   g_d2p[8];            // packed bias pairs
__device__ float g_Wa2[32];
__device__ float g_ba2s;

// ---------------- weight folding kernel (multi-block grid-stride) ----------------
__global__ void disarm_prep(
    const float* __restrict__ Wf1, const float* __restrict__ bf1,
    const float* __restrict__ gf1, const float* __restrict__ btf1,
    const float* __restrict__ Wf2, const float* __restrict__ bf2,
    const float* __restrict__ Ws1, const float* __restrict__ bs1,
    const float* __restrict__ gs1, const float* __restrict__ bts1,
    const float* __restrict__ Ws2, const float* __restrict__ bs2,
    const float* __restrict__ gs2, const float* __restrict__ bts2,
    const float* __restrict__ Ws3, const float* __restrict__ bs3,
    const float* __restrict__ Wa1, const float* __restrict__ ba1,
    const float* __restrict__ ga1, const float* __restrict__ bta1,
    const float* __restrict__ Wa2, const float* __restrict__ ba2)
{
    const float inv = rsqrtf(1.0f + 1e-5f);
    const int t  = threadIdx.x + blockIdx.x * blockDim.x;
    const int nt = blockDim.x * gridDim.x;
    const int lt = threadIdx.x;

    auto wt = [&](int r, int c) -> float {
        return gf1[r] * inv * Wf1[r * FDc + c];
    };
    for (int i = t; i < 4 * 8 * 32; i += nt) {
        int tile = i >> 8, kk = (i >> 5) & 7, lane = i & 31;
        int g8 = lane >> 2, t4 = lane & 3;
        int r = 16 * tile + g8, c = 16 * kk + 2 * t4;
        uint4 v;
        v.x = pkh2(wt(r,     c), wt(r,     c + 1));
        v.y = pkh2(wt(r + 8, c), wt(r + 8, c + 1));
        v.z = pkh2(wt(r,     c + 8), wt(r,     c + 9));
        v.w = pkh2(wt(r + 8, c + 8), wt(r + 8, c + 9));
        g_WhF[i] = v;
    }
    auto m2 = [&](int o, int kk) -> float {
        float acc = 0.0f;
        if (kk < 64) {
            for (int j = 0; j < 32; ++j) acc += Wa1[o*64 + 32 + j] * Wf2[j*64 + kk];
        } else {
            for (int mq = 0; mq < 32; ++mq) acc += Wa1[o*64 + mq] * Ws3[mq*16 + (kk - 64)];
        }
        return ga1[o] * inv * acc;
    };
    // k-pair unit map: pair p<32 -> hidden rows (16(p>>3)+(p&7)), +8;
    //                  p>=32 -> spatial units 2(p-32), +1
    auto U = [&](int p, int e) -> int {
        if (p < 32) return 16 * (p >> 3) + (p & 7) + 8 * e;
        return 64 + 2 * (p - 32) + e;
    };
    for (int i = t; i < 2 * 5 * 32; i += nt) {
        int m = i / (5 * 32), kk2 = (i / 32) % 5, lane = i & 31;
        int g8 = lane >> 2, t4 = lane & 3;
        int r = 16 * m + g8;
        int p = 8 * kk2 + t4;
        uint4 v;
        v.x = pkh2(m2(r,     U(p, 0)),     m2(r,     U(p, 1)));
        v.y = pkh2(m2(r + 8, U(p, 0)),     m2(r + 8, U(p, 1)));
        v.z = pkh2(m2(r,     U(p + 4, 0)), m2(r,     U(p + 4, 1)));
        v.w = pkh2(m2(r + 8, U(p + 4, 0)), m2(r + 8, U(p + 4, 1)));
        g_M2hF[i] = v;
    }
    if (blockIdx.x == 0) {
        for (int i = lt; i < 64; i += blockDim.x) g_c1[i] = gf1[i]*inv*bf1[i] + btf1[i];
        if (lt < 32) {
            float acc = 0.0f;
            for (int j = 0; j < 32; ++j) acc += Wa1[lt*64 + 32 + j] * bf2[j];
            for (int mq = 0; mq < 32; ++mq) acc += Wa1[lt*64 + mq] * bs3[mq];
            g_ca[lt] = ga1[lt]*inv*(acc + ba1[lt]) + bta1[lt];
        }
        if (lt < 8) {
            for (int i = 0; i < 3; ++i) g_B1[lt][i] = gs1[lt]*inv*Ws1[lt*3 + i];
            g_B1[lt][3] = 0.0f;
            g_d1[lt] = gs1[lt]*inv*bs1[lt] + bts1[lt];
        }
        if (lt < 64) {   // packed spatial layer-2: output pair (2j, 2j+1), input i
            int j = lt >> 3, i = lt & 7;
            float a = gs2[2*j]   * inv * Ws2[(2*j)  * 8 + i];
            float b = gs2[2*j+1] * inv * Ws2[(2*j+1)* 8 + i];
            g_B2p[j][i] = pk2(a, b);
        }
        if (lt < 8) {
            float a = gs2[2*lt]   * inv * bs2[2*lt]   + bts2[2*lt];
            float b = gs2[2*lt+1] * inv * bs2[2*lt+1] + bts2[2*lt+1];
            g_d2p[lt] = pk2(a, b);
        }
        if (lt < 32) g_Wa2[lt] = Wa2[lt];
        if (lt == 0) g_ba2s = ba2[0];
    }
}

// ---------------- smem layout (bytes) ----------------
#define XHS      72                         // u32 per channel-pair row
#define XHBUF    (64 * XHS * 4)             // 18432 B
#define CHS      72
#define SPS      72
#define SM_XH    0                          // 2 buffers: 36864
#define SM_CH    (2 * XHBUF)                // 32*72*4 = 9216 (hidden kpairs only)
#define SM_SP    (SM_CH + 9216)             // 8 grp * 8 rows * 72*4 = 18432
#define SM_PART  (SM_SP + 18432)            // 2 bufs * 2 * 64 * 4 = 1024
#define SM_C1    (SM_PART + 1024)           // 256
#define SM_CA    (SM_C1 + 256)              // 128
#define SM_WA2   (SM_CA + 128)              // 128
#define SM_B1    (SM_WA2 + 128)             // 128
#define SM_D1    (SM_B1 + 128)              // 32
#define SM_B2P   (SM_D1 + 32)               // 64 u64 = 512
#define SM_D2P   (SM_B2P + 512)             // 64
#define SM_BA2   (SM_D2P + 64)              // 16
#define SM_TOTAL (SM_BA2 + 16)

// ---------------- main fused kernel ----------------
// R12 skeleton, spatial branch hoisted: prologue computes tanh'd spatial
// k-pairs for ALL 8 groups (one s1v per anchor-instance, f32x2 matvec) into
// sSP[8]; the per-group loop loses spatial + loc loads; mma2 kk2=4 reads sSP[g].
__global__ void __launch_bounds__(256, 2) disarm_mma(
    const float* __restrict__ loc, const float* __restrict__ feat,
    float* __restrict__ out)
{
    extern __shared__ char smem[];
    u32* sXH = (u32*)(smem + SM_XH);
    u32* sCH = (u32*)(smem + SM_CH);
    u32* sSP = (u32*)(smem + SM_SP);
    float (*sPart)[2][64] = (float (*)[2][64])(smem + SM_PART);  // [buf][m][a]
    float* sc1   = (float*)(smem + SM_C1);
    float* sca   = (float*)(smem + SM_CA);
    float* sWa2v = (float*)(smem + SM_WA2);
    float (*sB1)[4] = (float (*)[4])(smem + SM_B1);
    float* sd1   = (float*)(smem + SM_D1);
    u64* sB2p    = (u64*)(smem + SM_B2P);    // [j*8 + i]
    u64* sd2p    = (u64*)(smem + SM_D2P);
    float* sba2  = (float*)(smem + SM_BA2);

    const int tid  = threadIdx.x;
    const int warp = tid >> 5;
    const int lane = tid & 31;
    const int g8   = lane >> 2;
    const int t4   = lane & 3;
    const int wM   = warp >> 1;   // mma1 row tile (0..3)
    const int wN   = warp & 1;    // mma1 anchor half (0..1)
    const int m    = warp & 1;    // mma2 row half
    const int nt   = warp >> 1;   // mma2 anchor 16-col tile

    const size_t cs = (size_t)NUMc * NAc;
    const int gp0 = blockIdx.x * GRPS;

    // X-staging indices
    const int cp0 = tid >> 4;      // channel-pair base; iter it uses cp0 + 16*it
    const int ab  = tid & 15;      // anchor block

    // ---- persistent A1 fragments (8 coalesced LDG.128) ----
    u32 A[32];
    {
        const uint4* aw = g_WhF + (size_t)wM * 8 * 32 + lane;
        #pragma unroll
        for (int kk = 0; kk < 8; ++kk) {
            uint4 v = __ldg(aw + kk * 32);
            A[4*kk+0] = v.x; A[4*kk+1] = v.y; A[4*kk+2] = v.z; A[4*kk+3] = v.w;
        }
    }
    // ---- persistent M2 fragments (5 coalesced LDG.128) ----
    u32 M[20];
    {
        const uint4* mw = g_M2hF + (size_t)m * 5 * 32 + lane;
        #pragma unroll
        for (int kk2 = 0; kk2 < 5; ++kk2) {
            uint4 v = __ldg(mw + kk2 * 32);
            M[4*kk2+0] = v.x; M[4*kk2+1] = v.y; M[4*kk2+2] = v.z; M[4*kk2+3] = v.w;
        }
    }

    // ---- stage small weights ----
    if (tid < 64) sc1[tid] = g_c1[tid];
    if (tid < 32) { sca[tid] = g_ca[tid]; sWa2v[tid] = g_Wa2[tid]; }
    if (tid < 32) sB1[tid>>2][tid&3] = g_B1[tid>>2][tid&3];
    if (tid < 8)  sd1[tid] = g_d1[tid];
    if (tid >= 128 && tid < 192) sB2p[tid-128] = g_B2p[(tid-128)>>3][(tid-128)&7];
    if (tid >= 192 && tid < 200) sd2p[tid-192] = g_d2p[tid-192];
    if (tid == 0) sba2[0] = g_ba2s;

    // ---- prologue: fill X half tile for group 0 ----
    {
        const int b = gp0 >> 10, p = gp0 & 1023;
        const float* fb = feat + (size_t)b * FDc * cs + (size_t)p * NAc;
        #pragma unroll
        for (int it = 0; it < 4; ++it) {
            const int cp = cp0 + 16 * it;
            float4 xa = __ldg((const float4*)(fb + (size_t)(2*cp  ) * cs) + ab);
            float4 xc = __ldg((const float4*)(fb + (size_t)(2*cp+1) * cs) + ab);
            uint4 w;
            w.x = pkh2(xa.x, xc.x); w.y = pkh2(xa.y, xc.y);
            w.z = pkh2(xa.z, xc.z); w.w = pkh2(xa.w, xc.w);
            *(uint4*)(sXH + cp * XHS + 4 * ab) = w;
        }
    }
    __syncthreads();   // weights staged (X0 published by the next sync)

    // ---- prologue: spatial branch for ALL 8 groups ----
    // 512 anchor-instances; thread handles 2. s1v computed once per instance;
    // 16x8 matvec in packed f32x2 over output pairs = sSP k-pair rows.
    #pragma unroll
    for (int j2 = 0; j2 < 2; ++j2) {
        const int idx = tid + 256 * j2;
        const int gi  = idx >> 6;           // group 0..7
        const int a   = idx & 63;           // anchor
        const int gp  = gp0 + gi;
        const int b   = gp >> 10;
        const int p   = gp & 1023;
        const float* lp = loc + (((size_t)(b*NUMc + p))*NAc + a) * 3;
        const float l0 = __ldg(lp), l1 = __ldg(lp + 1), l2 = __ldg(lp + 2);

        u64 sv[8];
        #pragma unroll
        for (int j = 0; j < 8; ++j) {
            float s = tanha(sB1[j][0]*l0 + sB1[j][1]*l1 + sB1[j][2]*l2 + sd1[j]);
            sv[j] = pk2(s, s);
        }
        u32* dst = sSP + (gi * 8) * SPS + a;
        #pragma unroll
        for (int j = 0; j < 8; ++j) {       // output pair (2j, 2j+1)
            u64 acc = sd2p[j];
            #pragma unroll
            for (int i = 0; i < 8; ++i) acc = ffma2(sB2p[j*8 + i], sv[i], acc);
            float ta, tb; upk2(acc, ta, tb);
            dst[j * SPS] = pkh2(tanha(ta), tanha(tb));
        }
    }
    __syncthreads();   // sSP + X0 published

    #pragma unroll 1
    for (int g = 0; g < GRPS; ++g) {
        const int gp = gp0 + g;
        u32* xb = sXH + (g & 1) * (64 * XHS);

        // ---- mma1: 32 fp16 mma/warp, 2 LDS.128 per kstep ----
        float D[4][4];
        #pragma unroll
        for (int n = 0; n < 4; ++n) { D[n][0]=0.f; D[n][1]=0.f; D[n][2]=0.f; D[n][3]=0.f; }
        #pragma unroll
        for (int kk = 0; kk < 8; ++kk) {
            const uint4 v0 = *(const uint4*)(xb + (8*kk + t4    ) * XHS + 32*wN + 4*g8);
            const uint4 v1 = *(const uint4*)(xb + (8*kk + t4 + 4) * XHS + 32*wN + 4*g8);
            mma_f16(D[0], A[4*kk], A[4*kk+1], A[4*kk+2], A[4*kk+3], v0.x, v1.x);
            mma_f16(D[1], A[4*kk], A[4*kk+1], A[4*kk+2], A[4*kk+3], v0.y, v1.y);
            mma_f16(D[2], A[4*kk], A[4*kk+1], A[4*kk+2], A[4*kk+3], v0.z, v1.z);
            mma_f16(D[3], A[4*kk], A[4*kk+1], A[4*kk+2], A[4*kk+3], v0.w, v1.w);
        }

        // ---- prefetch group g+1's X into registers (post-mma1) ----
        float4 q0a, q0b, q1a, q1b, q2a, q2b, q3a, q3b;
        if (g + 1 < GRPS) {
            const int gp1 = gp + 1;
            const int b1 = gp1 >> 10, p1 = gp1 & 1023;
            const float* fb1 = feat + (size_t)b1 * FDc * cs + (size_t)p1 * NAc;
            q0a = __ldg((const float4*)(fb1 + (size_t)(2*cp0      ) * cs) + ab);
            q0b = __ldg((const float4*)(fb1 + (size_t)(2*cp0 +  1) * cs) + ab);
            q1a = __ldg((const float4*)(fb1 + (size_t)(2*cp0 + 32) * cs) + ab);
            q1b = __ldg((const float4*)(fb1 + (size_t)(2*cp0 + 33) * cs) + ab);
            q2a = __ldg((const float4*)(fb1 + (size_t)(2*cp0 + 64) * cs) + ab);
            q2b = __ldg((const float4*)(fb1 + (size_t)(2*cp0 + 65) * cs) + ab);
            q3a = __ldg((const float4*)(fb1 + (size_t)(2*cp0 + 96) * cs) + ab);
            q3b = __ldg((const float4*)(fb1 + (size_t)(2*cp0 + 97) * cs) + ab);
        }

        // ---- epi1: tanh(H + c1) -> C k-pairs 0..31 (2 STS.128) ----
        {
            const int pp = 8*wM + g8;
            const float c1a = sc1[16*wM + g8];
            const float c1b = sc1[16*wM + g8 + 8];
            u32* cw = sCH + pp * CHS + 32*wN + 8*t4;
            uint4 w;
            w.x = pkh2(tanha(D[0][0] + c1a), tanha(D[0][2] + c1b));
            w.y = pkh2(tanha(D[1][0] + c1a), tanha(D[1][2] + c1b));
            w.z = pkh2(tanha(D[2][0] + c1a), tanha(D[2][2] + c1b));
            w.w = pkh2(tanha(D[3][0] + c1a), tanha(D[3][2] + c1b));
            *(uint4*)cw = w;
            w.x = pkh2(tanha(D[0][1] + c1a), tanha(D[0][3] + c1b));
            w.y = pkh2(tanha(D[1][1] + c1a), tanha(D[1][3] + c1b));
            w.z = pkh2(tanha(D[2][1] + c1a), tanha(D[2][3] + c1b));
            w.w = pkh2(tanha(D[3][1] + c1a), tanha(D[3][3] + c1b));
            *(uint4*)(cw + 4) = w;
        }
        __syncthreads();            // sC ready; xb reads done

        // ---- mma2: 10 fp16 mma/warp; kk2=4 reads spatial from sSP[g] ----
        float D2[2][4];
        D2[0][0]=0.f; D2[0][1]=0.f; D2[0][2]=0.f; D2[0][3]=0.f;
        D2[1][0]=0.f; D2[1][1]=0.f; D2[1][2]=0.f; D2[1][3]=0.f;
        #pragma unroll
        for (int kk2 = 0; kk2 < 4; ++kk2) {
            const uint2 w0 = *(const uint2*)(sCH + (8*kk2 + t4    ) * CHS + 16*nt + 2*g8);
            const uint2 w1 = *(const uint2*)(sCH + (8*kk2 + t4 + 4) * CHS + 16*nt + 2*g8);
            mma_f16(D2[0], M[4*kk2], M[4*kk2+1], M[4*kk2+2], M[4*kk2+3], w0.x, w1.x);
            mma_f16(D2[1], M[4*kk2], M[4*kk2+1], M[4*kk2+2], M[4*kk2+3], w0.y, w1.y);
        }
        {
            const u32* sp = sSP + (g * 8) * SPS + 16*nt + 2*g8;
            const uint2 w0 = *(const uint2*)(sp + t4 * SPS);
            const uint2 w1 = *(const uint2*)(sp + (t4 + 4) * SPS);
            mma_f16(D2[0], M[16], M[17], M[18], M[19], w0.x, w1.x);
            mma_f16(D2[1], M[16], M[17], M[18], M[19], w0.y, w1.y);
        }

        // ---- epi2: head partials (HW tanh) ----
        {
            const int ro = 16*m + g8;
            const float wa  = sWa2v[ro],   wb  = sWa2v[ro + 8];
            const float caa = sca[ro],     cab = sca[ro + 8];
            float p0 = wa * tanha(D2[0][0] + caa) + wb * tanha(D2[0][2] + cab); // +0
            float p2 = wa * tanha(D2[1][0] + caa) + wb * tanha(D2[1][2] + cab); // +1
            float p1 = wa * tanha(D2[0][1] + caa) + wb * tanha(D2[0][3] + cab); // +2
            float p3 = wa * tanha(D2[1][1] + caa) + wb * tanha(D2[1][3] + cab); // +3
            const unsigned m32 = 0xffffffffu;
            #pragma unroll
            for (int off = 4; off <= 16; off <<= 1) {
                p0 += __shfl_xor_sync(m32, p0, off);
                p1 += __shfl_xor_sync(m32, p1, off);
                p2 += __shfl_xor_sync(m32, p2, off);
                p3 += __shfl_xor_sync(m32, p3, off);
            }
            if (g8 == 0) {
                float4 v; v.x = p0; v.y = p2; v.z = p1; v.w = p3;
                *(float4*)&sPart[g & 1][m][16*nt + 4*t4] = v;
            }
        }

        // ---- convert + store X[g+1] (LDG latency fully elapsed by now) ----
        if (g + 1 < GRPS) {
            u32* xd = sXH + ((g + 1) & 1) * (64 * XHS);
            uint4 w;
            w.x = pkh2(q0a.x, q0b.x); w.y = pkh2(q0a.y, q0b.y);
            w.z = pkh2(q0a.z, q0b.z); w.w = pkh2(q0a.w, q0b.w);
            *(uint4*)(xd + (cp0     ) * XHS + 4 * ab) = w;
            w.x = pkh2(q1a.x, q1b.x); w.y = pkh2(q1a.y, q1b.y);
            w.z = pkh2(q1a.z, q1b.z); w.w = pkh2(q1a.w, q1b.w);
            *(uint4*)(xd + (cp0 + 16) * XHS + 4 * ab) = w;
            w.x = pkh2(q2a.x, q2b.x); w.y = pkh2(q2a.y, q2b.y);
            w.z = pkh2(q2a.z, q2b.z); w.w = pkh2(q2a.w, q2b.w);
            *(uint4*)(xd + (cp0 + 32) * XHS + 4 * ab) = w;
            w.x = pkh2(q3a.x, q3b.x); w.y = pkh2(q3a.y, q3b.y);
            w.z = pkh2(q3a.z, q3b.z); w.w = pkh2(q3a.w, q3b.w);
            *(uint4*)(xd + (cp0 + 48) * XHS + 4 * ab) = w;
        }
        __syncthreads();            // sPart + X[g+1] visible; sC reads done

        // ---- tail: warp 0 softmax + min-max norm (overlaps next mma1) ----
        if (warp == 0) {
            const int a0 = lane, a1 = lane + 32;
            const float* pb0 = sPart[g & 1][0];
            const float* pb1 = sPart[g & 1][1];
            const float lg0 = tanhp(pb0[a0] + pb1[a0] + sba2[0]);
            const float lg1 = tanhp(pb0[a1] + pb1[a1] + sba2[0]);

            const unsigned m32 = 0xffffffffu;
            float mx = fmaxf(lg0, lg1);
            float mn = fminf(lg0, lg1);
            #pragma unroll
            for (int off = 16; off > 0; off >>= 1) {
                mx = fmaxf(mx, __shfl_xor_sync(m32, mx, off));
                mn = fminf(mn, __shfl_xor_sync(m32, mn, off));
            }
            const float e0 = expf(lg0 - mx);
            const float e1 = expf(lg1 - mx);
            float ssum = e0 + e1;
            #pragma unroll
            for (int off = 16; off > 0; off >>= 1) ssum += __shfl_xor_sync(m32, ssum, off);
            const float invs = 1.0f / ssum;

            const float w0  = e0 * invs;
            const float w1  = e1 * invs;
            const float wmn = expf(mn - mx) * invs;
            const float wmx = invs;
            const float kk  = (1.0f + 1e-6f) / (wmx - wmn + 1e-6f);

            float* ob = out + (size_t)gp * NAc;
            float* on = ob + (size_t)BZc * NUMc * NAc;
            ob[a0] = w0;
            ob[a1] = w1;
            on[a0] = kk * (w0 - wmn);
            on[a1] = kk * (w1 - wmn);
        }
    }
}

// ---------------- launch ----------------
extern "C" void kernel_launch(void* const* d_in, const int* in_sizes, int n_in,
                              void* d_out, int out_size)
{
    const float* loc  = (const float*)d_in[0];
    const float* feat = (const float*)d_in[1];

    disarm_prep<<<16, 256>>>(
        (const float*)d_in[2],  (const float*)d_in[3],  (const float*)d_in[4],  (const float*)d_in[5],
        (const float*)d_in[6],  (const float*)d_in[7],
        (const float*)d_in[8],  (const float*)d_in[9],  (const float*)d_in[10], (const float*)d_in[11],
        (const float*)d_in[12], (const float*)d_in[13], (const float*)d_in[14], (const float*)d_in[15],
        (const float*)d_in[16], (const float*)d_in[17],
        (const float*)d_in[18], (const float*)d_in[19], (const float*)d_in[20], (const float*)d_in[21],
        (const float*)d_in[22], (const float*)d_in[23]);

    static int smem_set = 0;
    if (!smem_set) {
        cudaFuncSetAttribute(disarm_mma,
                             cudaFuncAttributeMaxDynamicSharedMemorySize, SM_TOTAL);
        smem_set = 1;
    }
    disarm_mma<<<(BZc * NUMc) / GRPS, 256, SM_TOTAL>>>(loc, feat, (float*)d_out);
}

// round 14
// speedup vs baseline: 1.4391x; 1.0557x over previous
#include <cuda_runtime.h>
#include <cuda_fp16.h>
#include <cstdint>

// Problem dims
#define BZc   8
#define NUMc  1024
#define NAc   64
#define FDc   128
#define GRPS  4          // (b,p) groups per CTA (grid 2048: 6.92 CTAs/slot -> 1.2% wave imbalance)

typedef unsigned int u32;
typedef unsigned long long u64;

// ---------------- helpers ----------------
__device__ __forceinline__ float tanha(float x) {           // HW approx
    float y; asm("tanh.approx.f32 %0, %1;" : "=f"(y) : "f"(x)); return y;
}
// Fast precise tanh: ex2 + rcp + 1 Newton step (~4e-7). Final logit only.
__device__ __forceinline__ float tanhp(float x) {
    float t; asm("ex2.approx.f32 %0, %1;" : "=f"(t) : "f"(x * 2.8853900817779268f));
    float d = 1.0f + t;
    float r; asm("rcp.approx.f32 %0, %1;" : "=f"(r) : "f"(d));
    r = fmaf(fmaf(-d, r, 1.0f), r, r);
    return fmaf(-2.0f, r, 1.0f);
}
__device__ __forceinline__ u32 pkh2(float a, float b) {
    __half2 h = __floats2half2_rn(a, b);
    return *(u32*)&h;
}
__device__ __forceinline__ u64 pk2(float a, float b) {
    u64 r; asm("mov.b64 %0, {%1,%2};" : "=l"(r) : "f"(a), "f"(b)); return r;
}
__device__ __forceinline__ void upk2(u64 v, float& a, float& b) {
    asm("mov.b64 {%0,%1}, %2;" : "=f"(a), "=f"(b) : "l"(v));
}
__device__ __forceinline__ u64 ffma2(u64 a, u64 b, u64 c) {
    u64 d; asm("fma.rn.f32x2 %0, %1, %2, %3;" : "=l"(d) : "l"(a), "l"(b), "l"(c)); return d;
}
__device__ __forceinline__ void mma_f16(float d[4],
    u32 a0, u32 a1, u32 a2, u32 a3, u32 b0, u32 b1)
{
    asm("mma.sync.aligned.m16n8k16.row.col.f32.f16.f16.f32 "
        "{%0,%1,%2,%3}, {%4,%5,%6,%7}, {%8,%9}, {%0,%1,%2,%3};"
        : "+f"(d[0]), "+f"(d[1]), "+f"(d[2]), "+f"(d[3])
        : "r"(a0), "r"(a1), "r"(a2), "r"(a3), "r"(b0), "r"(b1));
}

// ---------------- folded weight storage (fp16 fragment layouts) ----------------
__device__ uint4 g_WhF[4 * 8 * 32];   // A1 frags [tile(4)][kk(8)][lane(32)]
__device__ uint4 g_M2hF[2 * 5 * 32];  // M2 frags [m(2)][kk2(5)][lane(32)]
__device__ float g_c1[64];
__device__ float g_ca[32];
__device__ float g_B1[8][4];
__device__ float g_d1[8];
__device__ u64   g_B2p[8][8];         // packed output-pairs of folded Ws2
__device__ u64   g_d2p[8];            // packed bias pairs
__device__ float g_Wa2[32];
__device__ float g_ba2s;

// ---------------- weight folding kernel (multi-block grid-stride) ----------------
__global__ void disarm_prep(
    const float* __restrict__ Wf1, const float* __restrict__ bf1,
    const float* __restrict__ gf1, const float* __restrict__ btf1,
    const float* __restrict__ Wf2, const float* __restrict__ bf2,
    const float* __restrict__ Ws1, const float* __restrict__ bs1,
    const float* __restrict__ gs1, const float* __restrict__ bts1,
    const float* __restrict__ Ws2, const float* __restrict__ bs2,
    const float* __restrict__ gs2, const float* __restrict__ bts2,
    const float* __restrict__ Ws3, const float* __restrict__ bs3,
    const float* __restrict__ Wa1, const float* __restrict__ ba1,
    const float* __restrict__ ga1, const float* __restrict__ bta1,
    const float* __restrict__ Wa2, const float* __restrict__ ba2)
{
    const float inv = rsqrtf(1.0f + 1e-5f);
    const int t  = threadIdx.x + blockIdx.x * blockDim.x;
    const int nt = blockDim.x * gridDim.x;
    const int lt = threadIdx.x;

    auto wt = [&](int r, int c) -> float {
        return gf1[r] * inv * Wf1[r * FDc + c];
    };
    for (int i = t; i < 4 * 8 * 32; i += nt) {
        int tile = i >> 8, kk = (i >> 5) & 7, lane = i & 31;
        int g8 = lane >> 2, t4 = lane & 3;
        int r = 16 * tile + g8, c = 16 * kk + 2 * t4;
        uint4 v;
        v.x = pkh2(wt(r,     c), wt(r,     c + 1));
        v.y = pkh2(wt(r + 8, c), wt(r + 8, c + 1));
        v.z = pkh2(wt(r,     c + 8), wt(r,     c + 9));
        v.w = pkh2(wt(r + 8, c + 8), wt(r + 8, c + 9));
        g_WhF[i] = v;
    }
    auto m2 = [&](int o, int kk) -> float {
        float acc = 0.0f;
        if (kk < 64) {
            for (int j = 0; j < 32; ++j) acc += Wa1[o*64 + 32 + j] * Wf2[j*64 + kk];
        } else {
            for (int mq = 0; mq < 32; ++mq) acc += Wa1[o*64 + mq] * Ws3[mq*16 + (kk - 64)];
        }
        return ga1[o] * inv * acc;
    };
    // k-pair unit map: pair p<32 -> hidden rows (16(p>>3)+(p&7)), +8;
    //                  p>=32 -> spatial units 2(p-32), +1
    auto U = [&](int p, int e) -> int {
        if (p < 32) return 16 * (p >> 3) + (p & 7) + 8 * e;
        return 64 + 2 * (p - 32) + e;
    };
    for (int i = t; i < 2 * 5 * 32; i += nt) {
        int m = i / (5 * 32), kk2 = (i / 32) % 5, lane = i & 31;
        int g8 = lane >> 2, t4 = lane & 3;
        int r = 16 * m + g8;
        int p = 8 * kk2 + t4;
        uint4 v;
        v.x = pkh2(m2(r,     U(p, 0)),     m2(r,     U(p, 1)));
        v.y = pkh2(m2(r + 8, U(p, 0)),     m2(r + 8, U(p, 1)));
        v.z = pkh2(m2(r,     U(p + 4, 0)), m2(r,     U(p + 4, 1)));
        v.w = pkh2(m2(r + 8, U(p + 4, 0)), m2(r + 8, U(p + 4, 1)));
        g_M2hF[i] = v;
    }
    if (blockIdx.x == 0) {
        for (int i = lt; i < 64; i += blockDim.x) g_c1[i] = gf1[i]*inv*bf1[i] + btf1[i];
        if (lt < 32) {
            float acc = 0.0f;
            for (int j = 0; j < 32; ++j) acc += Wa1[lt*64 + 32 + j] * bf2[j];
            for (int mq = 0; mq < 32; ++mq) acc += Wa1[lt*64 + mq] * bs3[mq];
            g_ca[lt] = ga1[lt]*inv*(acc + ba1[lt]) + bta1[lt];
        }
        if (lt < 8) {
            for (int i = 0; i < 3; ++i) g_B1[lt][i] = gs1[lt]*inv*Ws1[lt*3 + i];
            g_B1[lt][3] = 0.0f;
            g_d1[lt] = gs1[lt]*inv*bs1[lt] + bts1[lt];
        }
        if (lt < 64) {   // packed spatial layer-2: output pair (2j, 2j+1), input i
            int j = lt >> 3, i = lt & 7;
            float a = gs2[2*j]   * inv * Ws2[(2*j)  * 8 + i];
            float b = gs2[2*j+1] * inv * Ws2[(2*j+1)* 8 + i];
            g_B2p[j][i] = pk2(a, b);
        }
        if (lt < 8) {
            float a = gs2[2*lt]   * inv * bs2[2*lt]   + bts2[2*lt];
            float b = gs2[2*lt+1] * inv * bs2[2*lt+1] + bts2[2*lt+1];
            g_d2p[lt] = pk2(a, b);
        }
        if (lt < 32) g_Wa2[lt] = Wa2[lt];
        if (lt == 0) g_ba2s = ba2[0];
    }
}

// ---------------- smem layout (bytes) ----------------
#define XHS      72                         // u32 per channel-pair row
#define XHBUF    (64 * XHS * 4)             // 18432 B
#define CHS      72
#define SPS      72
#define SM_XH    0                          // 2 buffers: 36864
#define SM_CH    (2 * XHBUF)                // 32*72*4 = 9216 (hidden kpairs only)
#define SM_SP    (SM_CH + 9216)             // 4 grp * 8 rows * 72*4 = 9216
#define SM_PART  (SM_SP + 9216)             // 2 bufs * 2 * 64 * 4 = 1024
#define SM_C1    (SM_PART + 1024)           // 256
#define SM_CA    (SM_C1 + 256)              // 128
#define SM_WA2   (SM_CA + 128)              // 128
#define SM_B1    (SM_WA2 + 128)             // 128
#define SM_D1    (SM_B1 + 128)              // 32
#define SM_B2P   (SM_D1 + 32)               // 64 u64 = 512
#define SM_D2P   (SM_B2P + 512)             // 64
#define SM_BA2   (SM_D2P + 64)              // 16
#define SM_TOTAL (SM_BA2 + 16)

// ---------------- main fused kernel ----------------
// R13 body with GRPS=4: finer CTA granularity kills the 15.6% wave-quantization
// tail (1024 CTAs / 296 slots = 3.46 -> makespan 4; 2048/296 = 6.92 -> 7, +1.2%).
// Spatial prologue: exactly 1 anchor-instance per thread (4 grp x 64 anchors).
__global__ void __launch_bounds__(256, 2) disarm_mma(
    const float* __restrict__ loc, const float* __restrict__ feat,
    float* __restrict__ out)
{
    extern __shared__ char smem[];
    u32* sXH = (u32*)(smem + SM_XH);
    u32* sCH = (u32*)(smem + SM_CH);
    u32* sSP = (u32*)(smem + SM_SP);
    float (*sPart)[2][64] = (float (*)[2][64])(smem + SM_PART);  // [buf][m][a]
    float* sc1   = (float*)(smem + SM_C1);
    float* sca   = (float*)(smem + SM_CA);
    float* sWa2v = (float*)(smem + SM_WA2);
    float (*sB1)[4] = (float (*)[4])(smem + SM_B1);
    float* sd1   = (float*)(smem + SM_D1);
    u64* sB2p    = (u64*)(smem + SM_B2P);    // [j*8 + i]
    u64* sd2p    = (u64*)(smem + SM_D2P);
    float* sba2  = (float*)(smem + SM_BA2);

    const int tid  = threadIdx.x;
    const int warp = tid >> 5;
    const int lane = tid & 31;
    const int g8   = lane >> 2;
    const int t4   = lane & 3;
    const int wM   = warp >> 1;   // mma1 row tile (0..3)
    const int wN   = warp & 1;    // mma1 anchor half (0..1)
    const int m    = warp & 1;    // mma2 row half
    const int nt   = warp >> 1;   // mma2 anchor 16-col tile

    const size_t cs = (size_t)NUMc * NAc;
    const int gp0 = blockIdx.x * GRPS;

    // X-staging indices
    const int cp0 = tid >> 4;      // channel-pair base; iter it uses cp0 + 16*it
    const int ab  = tid & 15;      // anchor block

    // ---- persistent A1 fragments (8 coalesced LDG.128) ----
    u32 A[32];
    {
        const uint4* aw = g_WhF + (size_t)wM * 8 * 32 + lane;
        #pragma unroll
        for (int kk = 0; kk < 8; ++kk) {
            uint4 v = __ldg(aw + kk * 32);
            A[4*kk+0] = v.x; A[4*kk+1] = v.y; A[4*kk+2] = v.z; A[4*kk+3] = v.w;
        }
    }
    // ---- persistent M2 fragments (5 coalesced LDG.128) ----
    u32 M[20];
    {
        const uint4* mw = g_M2hF + (size_t)m * 5 * 32 + lane;
        #pragma unroll
        for (int kk2 = 0; kk2 < 5; ++kk2) {
            uint4 v = __ldg(mw + kk2 * 32);
            M[4*kk2+0] = v.x; M[4*kk2+1] = v.y; M[4*kk2+2] = v.z; M[4*kk2+3] = v.w;
        }
    }

    // ---- stage small weights ----
    if (tid < 64) sc1[tid] = g_c1[tid];
    if (tid < 32) { sca[tid] = g_ca[tid]; sWa2v[tid] = g_Wa2[tid]; }
    if (tid < 32) sB1[tid>>2][tid&3] = g_B1[tid>>2][tid&3];
    if (tid < 8)  sd1[tid] = g_d1[tid];
    if (tid >= 128 && tid < 192) sB2p[tid-128] = g_B2p[(tid-128)>>3][(tid-128)&7];
    if (tid >= 192 && tid < 200) sd2p[tid-192] = g_d2p[tid-192];
    if (tid == 0) sba2[0] = g_ba2s;

    // ---- prologue: fill X half tile for group 0 ----
    {
        const int b = gp0 >> 10, p = gp0 & 1023;
        const float* fb = feat + (size_t)b * FDc * cs + (size_t)p * NAc;
        #pragma unroll
        for (int it = 0; it < 4; ++it) {
            const int cp = cp0 + 16 * it;
            float4 xa = __ldg((const float4*)(fb + (size_t)(2*cp  ) * cs) + ab);
            float4 xc = __ldg((const float4*)(fb + (size_t)(2*cp+1) * cs) + ab);
            uint4 w;
            w.x = pkh2(xa.x, xc.x); w.y = pkh2(xa.y, xc.y);
            w.z = pkh2(xa.z, xc.z); w.w = pkh2(xa.w, xc.w);
            *(uint4*)(sXH + cp * XHS + 4 * ab) = w;
        }
    }
    __syncthreads();   // weights staged (X0 published by the next sync)

    // ---- prologue: spatial branch for ALL 4 groups (1 instance/thread) ----
    {
        const int gi  = tid >> 6;           // group 0..3
        const int a   = tid & 63;           // anchor
        const int gp  = gp0 + gi;
        const int b   = gp >> 10;
        const int p   = gp & 1023;
        const float* lp = loc + (((size_t)(b*NUMc + p))*NAc + a) * 3;
        const float l0 = __ldg(lp), l1 = __ldg(lp + 1), l2 = __ldg(lp + 2);

        u64 sv[8];
        #pragma unroll
        for (int j = 0; j < 8; ++j) {
            float s = tanha(sB1[j][0]*l0 + sB1[j][1]*l1 + sB1[j][2]*l2 + sd1[j]);
            sv[j] = pk2(s, s);
        }
        u32* dst = sSP + (gi * 8) * SPS + a;
        #pragma unroll
        for (int j = 0; j < 8; ++j) {       // output pair (2j, 2j+1)
            u64 acc = sd2p[j];
            #pragma unroll
            for (int i = 0; i < 8; ++i) acc = ffma2(sB2p[j*8 + i], sv[i], acc);
            float ta, tb; upk2(acc, ta, tb);
            dst[j * SPS] = pkh2(tanha(ta), tanha(tb));
        }
    }
    __syncthreads();   // sSP + X0 published

    #pragma unroll 1
    for (int g = 0; g < GRPS; ++g) {
        const int gp = gp0 + g;
        u32* xb = sXH + (g & 1) * (64 * XHS);

        // ---- mma1: 32 fp16 mma/warp, 2 LDS.128 per kstep ----
        float D[4][4];
        #pragma unroll
        for (int n = 0; n < 4; ++n) { D[n][0]=0.f; D[n][1]=0.f; D[n][2]=0.f; D[n][3]=0.f; }
        #pragma unroll
        for (int kk = 0; kk < 8; ++kk) {
            const uint4 v0 = *(const uint4*)(xb + (8*kk + t4    ) * XHS + 32*wN + 4*g8);
            const uint4 v1 = *(const uint4*)(xb + (8*kk + t4 + 4) * XHS + 32*wN + 4*g8);
            mma_f16(D[0], A[4*kk], A[4*kk+1], A[4*kk+2], A[4*kk+3], v0.x, v1.x);
            mma_f16(D[1], A[4*kk], A[4*kk+1], A[4*kk+2], A[4*kk+3], v0.y, v1.y);
            mma_f16(D[2], A[4*kk], A[4*kk+1], A[4*kk+2], A[4*kk+3], v0.z, v1.z);
            mma_f16(D[3], A[4*kk], A[4*kk+1], A[4*kk+2], A[4*kk+3], v0.w, v1.w);
        }

        // ---- prefetch group g+1's X into registers (post-mma1) ----
        float4 q0a, q0b, q1a, q1b, q2a, q2b, q3a, q3b;
        if (g + 1 < GRPS) {
            const int gp1 = gp + 1;
            const int b1 = gp1 >> 10, p1 = gp1 & 1023;
            const float* fb1 = feat + (size_t)b1 * FDc * cs + (size_t)p1 * NAc;
            q0a = __ldg((const float4*)(fb1 + (size_t)(2*cp0      ) * cs) + ab);
            q0b = __ldg((const float4*)(fb1 + (size_t)(2*cp0 +  1) * cs) + ab);
            q1a = __ldg((const float4*)(fb1 + (size_t)(2*cp0 + 32) * cs) + ab);
            q1b = __ldg((const float4*)(fb1 + (size_t)(2*cp0 + 33) * cs) + ab);
            q2a = __ldg((const float4*)(fb1 + (size_t)(2*cp0 + 64) * cs) + ab);
            q2b = __ldg((const float4*)(fb1 + (size_t)(2*cp0 + 65) * cs) + ab);
            q3a = __ldg((const float4*)(fb1 + (size_t)(2*cp0 + 96) * cs) + ab);
            q3b = __ldg((const float4*)(fb1 + (size_t)(2*cp0 + 97) * cs) + ab);
        }

        // ---- epi1: tanh(H + c1) -> C k-pairs 0..31 (2 STS.128) ----
        {
            const int pp = 8*wM + g8;
            const float c1a = sc1[16*wM + g8];
            const float c1b = sc1[16*wM + g8 + 8];
            u32* cw = sCH + pp * CHS + 32*wN + 8*t4;
            uint4 w;
            w.x = pkh2(tanha(D[0][0] + c1a), tanha(D[0][2] + c1b));
            w.y = pkh2(tanha(D[1][0] + c1a), tanha(D[1][2] + c1b));
            w.z = pkh2(tanha(D[2][0] + c1a), tanha(D[2][2] + c1b));
            w.w = pkh2(tanha(D[3][0] + c1a), tanha(D[3][2] + c1b));
            *(uint4*)cw = w;
            w.x = pkh2(tanha(D[0][1] + c1a), tanha(D[0][3] + c1b));
            w.y = pkh2(tanha(D[1][1] + c1a), tanha(D[1][3] + c1b));
            w.z = pkh2(tanha(D[2][1] + c1a), tanha(D[2][3] + c1b));
            w.w = pkh2(tanha(D[3][1] + c1a), tanha(D[3][3] + c1b));
            *(uint4*)(cw + 4) = w;
        }
        __syncthreads();            // sC ready; xb reads done

        // ---- mma2: 10 fp16 mma/warp; kk2=4 reads spatial from sSP[g] ----
        float D2[2][4];
        D2[0][0]=0.f; D2[0][1]=0.f; D2[0][2]=0.f; D2[0][3]=0.f;
        D2[1][0]=0.f; D2[1][1]=0.f; D2[1][2]=0.f; D2[1][3]=0.f;
        #pragma unroll
        for (int kk2 = 0; kk2 < 4; ++kk2) {
            const uint2 w0 = *(const uint2*)(sCH + (8*kk2 + t4    ) * CHS + 16*nt + 2*g8);
            const uint2 w1 = *(const uint2*)(sCH + (8*kk2 + t4 + 4) * CHS + 16*nt + 2*g8);
            mma_f16(D2[0], M[4*kk2], M[4*kk2+1], M[4*kk2+2], M[4*kk2+3], w0.x, w1.x);
            mma_f16(D2[1], M[4*kk2], M[4*kk2+1], M[4*kk2+2], M[4*kk2+3], w0.y, w1.y);
        }
        {
            const u32* sp = sSP + (g * 8) * SPS + 16*nt + 2*g8;
            const uint2 w0 = *(const uint2*)(sp + t4 * SPS);
            const uint2 w1 = *(const uint2*)(sp + (t4 + 4) * SPS);
            mma_f16(D2[0], M[16], M[17], M[18], M[19], w0.x, w1.x);
            mma_f16(D2[1], M[16], M[17], M[18], M[19], w0.y, w1.y);
        }

        // ---- epi2: head partials (HW tanh) ----
        {
            const int ro = 16*m + g8;
            const float wa  = sWa2v[ro],   wb  = sWa2v[ro + 8];
            const float caa = sca[ro],     cab = sca[ro + 8];
            float p0 = wa * tanha(D2[0][0] + caa) + wb * tanha(D2[0][2] + cab); // +0
            float p2 = wa * tanha(D2[1][0] + caa) + wb * tanha(D2[1][2] + cab); // +1
            float p1 = wa * tanha(D2[0][1] + caa) + wb * tanha(D2[0][3] + cab); // +2
            float p3 = wa * tanha(D2[1][1] + caa) + wb * tanha(D2[1][3] + cab); // +3
            const unsigned m32 = 0xffffffffu;
            #pragma unroll
            for (int off = 4; off <= 16; off <<= 1) {
                p0 += __shfl_xor_sync(m32, p0, off);
                p1 += __shfl_xor_sync(m32, p1, off);
                p2 += __shfl_xor_sync(m32, p2, off);
                p3 += __shfl_xor_sync(m32, p3, off);
            }
            if (g8 == 0) {
                float4 v; v.x = p0; v.y = p2; v.z = p1; v.w = p3;
                *(float4*)&sPart[g & 1][m][16*nt + 4*t4] = v;
            }
        }

        // ---- convert + store X[g+1] (LDG latency fully elapsed by now) ----
        if (g + 1 < GRPS) {
            u32* xd = sXH + ((g + 1) & 1) * (64 * XHS);
            uint4 w;
            w.x = pkh2(q0a.x, q0b.x); w.y = pkh2(q0a.y, q0b.y);
            w.z = pkh2(q0a.z, q0b.z); w.w = pkh2(q0a.w, q0b.w);
            *(uint4*)(xd + (cp0     ) * XHS + 4 * ab) = w;
            w.x = pkh2(q1a.x, q1b.x); w.y = pkh2(q1a.y, q1b.y);
            w.z = pkh2(q1a.z, q1b.z); w.w = pkh2(q1a.w, q1b.w);
            *(uint4*)(xd + (cp0 + 16) * XHS + 4 * ab) = w;
            w.x = pkh2(q2a.x, q2b.x); w.y = pkh2(q2a.y, q2b.y);
            w.z = pkh2(q2a.z, q2b.z); w.w = pkh2(q2a.w, q2b.w);
            *(uint4*)(xd + (cp0 + 32) * XHS + 4 * ab) = w;
            w.x = pkh2(q3a.x, q3b.x); w.y = pkh2(q3a.y, q3b.y);
            w.z = pkh2(q3a.z, q3b.z); w.w = pkh2(q3a.w, q3b.w);
            *(uint4*)(xd + (cp0 + 48) * XHS + 4 * ab) = w;
        }
        __syncthreads();            // sPart + X[g+1] visible; sC reads done

        // ---- tail: warp 0 softmax + min-max norm (overlaps next mma1) ----
        if (warp == 0) {
            const int a0 = lane, a1 = lane + 32;
            const float* pb0 = sPart[g & 1][0];
            const float* pb1 = sPart[g & 1][1];
            const float lg0 = tanhp(pb0[a0] + pb1[a0] + sba2[0]);
            const float lg1 = tanhp(pb0[a1] + pb1[a1] + sba2[0]);

            const unsigned m32 = 0xffffffffu;
            float mx = fmaxf(lg0, lg1);
            float mn = fminf(lg0, lg1);
            #pragma unroll
            for (int off = 16; off > 0; off >>= 1) {
                mx = fmaxf(mx, __shfl_xor_sync(m32, mx, off));
                mn = fminf(mn, __shfl_xor_sync(m32, mn, off));
            }
            const float e0 = expf(lg0 - mx);
            const float e1 = expf(lg1 - mx);
            float ssum = e0 + e1;
            #pragma unroll
            for (int off = 16; off > 0; off >>= 1) ssum += __shfl_xor_sync(m32, ssum, off);
            const float invs = 1.0f / ssum;

            const float w0  = e0 * invs;
            const float w1  = e1 * invs;
            const float wmn = expf(mn - mx) * invs;
            const float wmx = invs;
            const float kk  = (1.0f + 1e-6f) / (wmx - wmn + 1e-6f);

            float* ob = out + (size_t)gp * NAc;
            float* on = ob + (size_t)BZc * NUMc * NAc;
            ob[a0] = w0;
            ob[a1] = w1;
            on[a0] = kk * (w0 - wmn);
            on[a1] = kk * (w1 - wmn);
        }
    }
}

// ---------------- launch ----------------
extern "C" void kernel_launch(void* const* d_in, const int* in_sizes, int n_in,
                              void* d_out, int out_size)
{
    const float* loc  = (const float*)d_in[0];
    const float* feat = (const float*)d_in[1];

    disarm_prep<<<16, 256>>>(
        (const float*)d_in[2],  (const float*)d_in[3],  (const float*)d_in[4],  (const float*)d_in[5],
        (const float*)d_in[6],  (const float*)d_in[7],
        (const float*)d_in[8],  (const float*)d_in[9],  (const float*)d_in[10], (const float*)d_in[11],
        (const float*)d_in[12], (const float*)d_in[13], (const float*)d_in[14], (const float*)d_in[15],
        (const float*)d_in[16], (const float*)d_in[17],
        (const float*)d_in[18], (const float*)d_in[19], (const float*)d_in[20], (const float*)d_in[21],
        (const float*)d_in[22], (const float*)d_in[23]);

    static int smem_set = 0;
    if (!smem_set) {
        cudaFuncSetAttribute(disarm_mma,
                             cudaFuncAttributeMaxDynamicSharedMemorySize, SM_TOTAL);
        smem_set = 1;
    }
    disarm_mma<<<(BZc * NUMc) / GRPS, 256, SM_TOTAL>>>(loc, feat, (float*)d_out);
}